// round 1
// baseline (speedup 1.0000x reference)
#include <cuda_runtime.h>
#include <math.h>

#define NEDGE 65536
#define NATOM 2048
#define NRADB 24
#define NCOMP 5
#define KTOT  69
#define FDIM  216            // 24 * 9
#define EMBD  16
#define TILE  32
#define NCELL (NRADB * 70)   // 1680 accumulator cells (69 angular + 1 two-body per radial)
#define CPT   7              // cells per thread (ceil 1680/256)

// ---------------- scratch (static device globals; no runtime allocation) ----------------
__device__ int   g_lx[KTOT], g_ly[KTOT], g_lz[KTOT], g_izk[KTOT];
__device__ float g_fnorm[KTOT], g_lam[KTOT];
__constant__ int KOFF[5] = {0, 4, 14, 34, 69};

__device__ int   d_seg[NATOM + 1];
__device__ float d_emb[NATOM * EMBD];
__device__ float d_feat[NATOM * FDIM];
__device__ float d_h1[NATOM * 256];
__device__ float d_h2[NATOM * 128];

__device__ __forceinline__ float silu_f(float x) { return x / (1.f + expf(-x)); }

__device__ __forceinline__ float powi(float b, int l) {
    float r = 1.f;
#pragma unroll
    for (int i = 0; i < 4; i++) if (i < l) r *= b;
    return r;
}

// ---------------- table init (deterministic, rebuilt every launch) ----------------
__global__ void init_tables() {
    if (threadIdx.x == 0 && blockIdx.x == 0) {
        const int fact[5] = {1, 1, 2, 6, 24};
        int idx = 0;
        for (int iz = 0; iz < 4; iz++) {
            int z = iz + 1;
            for (int n = 0; n <= z; n++)
                for (int lx = 0; lx <= n; lx++)
                    for (int ly = 0; ly <= n - lx; ly++) {
                        int lz = n - lx - ly;
                        g_lx[idx] = lx; g_ly[idx] = ly; g_lz[idx] = lz;
                        g_izk[idx] = iz;
                        g_fnorm[idx] = (float)fact[z] /
                            (float)(fact[z - n] * fact[lx] * fact[ly] * fact[lz]);
                        g_lam[idx] = (n & 1) ? -1.f : 1.f;
                        idx++;
                    }
        }
    }
}

// ---------------- segment offsets (first_atom_idx is sorted) ----------------
__global__ void seg_kernel(const int* __restrict__ fia) {
    int a = blockIdx.x * blockDim.x + threadIdx.x;
    if (a <= NATOM) {
        int lo = 0, hi = NEDGE;
        while (lo < hi) {
            int mid = (lo + hi) >> 1;
            if (fia[mid] < a) lo = mid + 1; else hi = mid;
        }
        d_seg[a] = lo;
    }
}

// ---------------- per-atom feature kernel ----------------
// One CTA per atom. Tile of up to 32 edges: phase A (8 warps x 4 edges) computes the
// radial MLP (24->64->120 with silu) and the 69 angular monomials into shared; phase B
// accumulates the 24x70 moment matrix in per-thread registers (conflict-free, no atomics).
__global__ __launch_bounds__(256, 3) void feature_kernel(
    const float* __restrict__ rij,
    const float* __restrict__ Wr1, const float* __restrict__ br1,
    const float* __restrict__ Wr2, const float* __restrict__ br2,
    const float* __restrict__ Ws1, const float* __restrict__ bs1,
    const float* __restrict__ Ws2, const float* __restrict__ bs2,
    const int* __restrict__ species)
{
    extern __shared__ float sm[];
    float* Wr1s = sm;                    // 24*64 = 1536
    float* br1s = Wr1s + NRADB * 64;     // 64
    float* Wr2s = br1s + 64;             // 64*120 = 7680
    float* br2s = Wr2s + 64 * 120;       // 120
    float* rads = br2s + 120;            // 32*120 = 3840
    float* gvs  = rads + TILE * 120;     // 32*72  = 2304
    float* gis  = gvs + TILE * 72;       // 1680
    float* ebuf = gis + NCELL;           // 8*88   = 704
    float* hsp  = ebuf + 8 * 88;         // 32

    int tid = threadIdx.x;
    int a = blockIdx.x;

    for (int i = tid; i < NRADB * 64; i += 256) Wr1s[i] = Wr1[i];
    if (tid < 64)  br1s[tid] = br1[tid];
    for (int i = tid; i < 64 * 120; i += 256) Wr2s[i] = Wr2[i];
    if (tid < 120) br2s[tid] = br2[tid];

    // species embedding: silu(Ws1[s]+bs1) @ Ws2 + bs2
    int sidx = species[a];
    if (tid < 32) hsp[tid] = silu_f(Ws1[sidx * 32 + tid] + bs1[tid]);
    __syncthreads();
    if (tid < EMBD) {
        float acc = bs2[tid];
        for (int i = 0; i < 32; i++) acc += hsp[i] * Ws2[i * EMBD + tid];
        d_emb[a * EMBD + tid] = acc;
    }

    // per-thread moment cells: cell = r*70 + k; k<69 angular, k==69 two-body
    float acc[CPT];
    int radoff[CPT], gvk[CPT];
#pragma unroll
    for (int c = 0; c < CPT; c++) {
        int cell = tid + c * 256;
        acc[c] = 0.f;
        if (cell < NCELL) {
            int r = cell / 70, k = cell % 70;
            if (k < KTOT) { radoff[c] = r * NCOMP + g_izk[k] + 1; gvk[c] = k; }
            else          { radoff[c] = r * NCOMP;                gvk[c] = -1; }
        } else gvk[c] = -2;
    }

    int beg = d_seg[a], end = d_seg[a + 1];
    int wid = tid >> 5, lane = tid & 31;
    float* bas = ebuf + wid * 88;
    float* hh  = bas + 24;

    for (int pos = beg; pos < end; pos += TILE) {
        int nE = min(TILE, end - pos);
        // ---- phase A: each warp computes 4 edges ----
        for (int i = 0; i < 4; i++) {
            int slot = wid * 4 + i;
            if (slot < nE) {
                int e = pos + slot;
                float x = rij[e * 3], y = rij[e * 3 + 1], z = rij[e * 3 + 2];
                float r = sqrtf(x * x + y * y + z * z);
                float inv = 1.f / r;
                float ux = x * inv + 1e-12f;
                float uy = y * inv + 1e-12f;
                float uz = z * inv + 1e-12f;
                float rc = fminf(r, 6.f);
                float fcv = 0.5f * (cosf(rc * 0.52359877559829887f) + 1.f);
                if (lane < NRADB) {
                    float d = r - (6.f / 23.f) * (float)lane;
                    bas[lane] = expf(-8.f * d * d) * fcv;   // 1/(2*0.25^2) = 8
                }
                __syncwarp();
#pragma unroll
                for (int q = 0; q < 2; q++) {
                    int j = lane + q * 32;
                    float s = br1s[j];
#pragma unroll
                    for (int k = 0; k < NRADB; k++) s += bas[k] * Wr1s[k * 64 + j];
                    hh[j] = silu_f(s);
                }
                __syncwarp();
#pragma unroll
                for (int q = 0; q < 4; q++) {
                    int j = lane + q * 32;
                    if (j < 120) {
                        float s = br2s[j];
#pragma unroll 8
                        for (int k = 0; k < 64; k++) s += hh[k] * Wr2s[k * 120 + j];
                        rads[slot * 120 + j] = silu_f(s);
                    }
                }
#pragma unroll
                for (int q = 0; q < 3; q++) {
                    int k = lane + q * 32;
                    if (k < KTOT) {
                        gvs[slot * 72 + k] = g_fnorm[k] *
                            powi(ux, g_lx[k]) * powi(uy, g_ly[k]) * powi(uz, g_lz[k]);
                    }
                }
            }
        }
        __syncthreads();
        // ---- phase B: register accumulation over the tile's edges ----
#pragma unroll
        for (int c = 0; c < CPT; c++) {
            if (gvk[c] == -2) continue;
            int ro = radoff[c];
            float aa = acc[c];
            if (gvk[c] >= 0) {
                int gk = gvk[c];
                for (int e = 0; e < nE; e++) aa += rads[e * 120 + ro] * gvs[e * 72 + gk];
            } else {
                for (int e = 0; e < nE; e++) aa += rads[e * 120 + ro];
            }
            acc[c] = aa;
        }
        __syncthreads();
    }

#pragma unroll
    for (int c = 0; c < CPT; c++) {
        int cell = tid + c * 256;
        if (cell < NCELL) gis[cell] = acc[c];
    }
    __syncthreads();

    // features: [feat0 | z1+ z1- | z2+ z2- | z3+ z3- | z4+ z4-], 24 each
    if (tid < FDIM) {
        int grp = tid / NRADB, r = tid % NRADB;
        float v;
        if (grp == 0) {
            v = gis[r * 70 + KTOT];
        } else {
            int iz = (grp - 1) >> 1;
            int neg = (grp - 1) & 1;
            float ssum = 0.f;
            for (int k = KOFF[iz]; k < KOFF[iz + 1]; k++) {
                float g = gis[r * 70 + k];
                ssum += g * g * (neg ? g_lam[k] : 1.f);
            }
            v = ssum * (1.0f / (float)(1 << iz));   // 2^(1-z), z = iz+1
        }
        d_feat[a * FDIM + tid] = v;
    }
}

// ---------------- tiled fp32 GEMM + bias + silu ----------------
// GEN_A: A[a][k] = feat[a][k>>4] * emb[a][k&15] (x = feat (x) emb, generated on the fly)
template <bool GEN_A>
__global__ __launch_bounds__(256) void gemm_silu_k(
    const float* __restrict__ A, const float* __restrict__ B,
    const float* __restrict__ bias, float* __restrict__ C,
    int M, int N, int K,
    const float* __restrict__ feat, const float* __restrict__ emb)
{
    const int BM = 64, BN = 64, BK = 32;
    __shared__ float As[BK][BM + 1];
    __shared__ float Bs[BK][BN + 1];
    int tid = threadIdx.x;
    int tx = tid % 16, ty = tid / 16;
    int row0 = blockIdx.x * BM, col0 = blockIdx.y * BN;
    float accum[4][4];
#pragma unroll
    for (int i = 0; i < 4; i++)
#pragma unroll
        for (int j = 0; j < 4; j++) accum[i][j] = 0.f;

    for (int k0 = 0; k0 < K; k0 += BK) {
        for (int i = tid; i < BM * BK; i += 256) {
            int m = i / BK, k = i % BK;
            float v;
            if (GEN_A) {
                int kk = k0 + k;
                v = feat[(row0 + m) * FDIM + (kk >> 4)] * emb[(row0 + m) * EMBD + (kk & 15)];
            } else {
                v = A[(row0 + m) * K + k0 + k];
            }
            As[k][m] = v;
        }
        for (int i = tid; i < BK * BN; i += 256) {
            int k = i / BN, n = i % BN;
            Bs[k][n] = B[(k0 + k) * N + col0 + n];
        }
        __syncthreads();
#pragma unroll
        for (int k = 0; k < BK; k++) {
            float av[4], bv[4];
#pragma unroll
            for (int i = 0; i < 4; i++) av[i] = As[k][ty * 4 + i];
#pragma unroll
            for (int j = 0; j < 4; j++) bv[j] = Bs[k][tx * 4 + j];
#pragma unroll
            for (int i = 0; i < 4; i++)
#pragma unroll
                for (int j = 0; j < 4; j++) accum[i][j] += av[i] * bv[j];
        }
        __syncthreads();
    }
#pragma unroll
    for (int i = 0; i < 4; i++) {
        int row = row0 + ty * 4 + i;
#pragma unroll
        for (int j = 0; j < 4; j++) {
            int col = col0 + tx * 4 + j;
            C[row * N + col] = silu_f(accum[i][j] + bias[col]);
        }
    }
}

// ---------------- final reduction: e_a = h2 . Wa3 + ba3 ; out = sum_a e_a ----------------
__global__ void zero_out_k(float* out) { out[0] = 0.f; }

__global__ void final_kernel(const float* __restrict__ Wa3,
                             const float* __restrict__ ba3, float* out) {
    int gt = blockIdx.x * blockDim.x + threadIdx.x;
    int a = gt >> 5, lane = gt & 31;
    if (a < NATOM) {
        float s = 0.f;
#pragma unroll
        for (int i = lane; i < 128; i += 32) s += d_h2[a * 128 + i] * Wa3[i];
#pragma unroll
        for (int o = 16; o; o >>= 1) s += __shfl_xor_sync(0xffffffffu, s, o);
        if (lane == 0) atomicAdd(out, s + ba3[0]);
    }
}

// ---------------- launch ----------------
extern "C" void kernel_launch(void* const* d_in, const int* in_sizes, int n_in,
                              void* d_out, int out_size) {
    (void)in_sizes; (void)n_in; (void)out_size;
    const float* rij = (const float*)d_in[0];
    const float* Wr1 = (const float*)d_in[1];
    const float* br1 = (const float*)d_in[2];
    const float* Wr2 = (const float*)d_in[3];
    const float* br2 = (const float*)d_in[4];
    const float* Ws1 = (const float*)d_in[5];
    const float* bs1 = (const float*)d_in[6];
    const float* Ws2 = (const float*)d_in[7];
    const float* bs2 = (const float*)d_in[8];
    const float* Wa1 = (const float*)d_in[9];
    const float* ba1 = (const float*)d_in[10];
    const float* Wa2 = (const float*)d_in[11];
    const float* ba2 = (const float*)d_in[12];
    const float* Wa3 = (const float*)d_in[13];
    const float* ba3 = (const float*)d_in[14];
    const int*   fia     = (const int*)d_in[15];
    const int*   species = (const int*)d_in[16];
    float* out = (float*)d_out;

    void *p_feat, *p_emb, *p_h1, *p_h2;
    cudaGetSymbolAddress(&p_feat, d_feat);
    cudaGetSymbolAddress(&p_emb,  d_emb);
    cudaGetSymbolAddress(&p_h1,   d_h1);
    cudaGetSymbolAddress(&p_h2,   d_h2);

    init_tables<<<1, 1>>>();
    seg_kernel<<<(NATOM + 1 + 255) / 256, 256>>>(fia);

    const int SMEMB = (1536 + 64 + 7680 + 120 + TILE * 120 + TILE * 72 + NCELL + 8 * 88 + 32) * 4;
    cudaFuncSetAttribute(feature_kernel, cudaFuncAttributeMaxDynamicSharedMemorySize, SMEMB);
    feature_kernel<<<NATOM, 256, SMEMB>>>(rij, Wr1, br1, Wr2, br2,
                                          Ws1, bs1, Ws2, bs2, species);

    gemm_silu_k<true><<<dim3(NATOM / 64, 256 / 64), 256>>>(
        nullptr, Wa1, ba1, (float*)p_h1, NATOM, 256, FDIM * EMBD,
        (const float*)p_feat, (const float*)p_emb);

    gemm_silu_k<false><<<dim3(NATOM / 64, 128 / 64), 256>>>(
        (const float*)p_h1, Wa2, ba2, (float*)p_h2, NATOM, 128, 256,
        nullptr, nullptr);

    zero_out_k<<<1, 1>>>(out);
    final_kernel<<<NATOM * 32 / 256, 256>>>(Wa3, ba3, out);
}

// round 3
// speedup vs baseline: 1.6581x; 1.6581x over previous
#include <cuda_runtime.h>
#include <cuda_bf16.h>
#include <math.h>
#include <cstdint>

#define NEDGE 65536
#define NATOM 2048
#define NRADB 24
#define NCOMP 5
#define KTOT  69
#define FDIM  216            // 24 * 9
#define EMBD  16
#define TILE  32
#define NCELL (NRADB * 70)
#define CPT   7
#define KTOTAL 3456          // FDIM * EMBD
#define KSPLIT 4
#define ITERS  27            // KTOTAL / KSPLIT / 32

// ---------------- scratch (static device globals) ----------------
__device__ int   g_lx[KTOT], g_ly[KTOT], g_lz[KTOT], g_izk[KTOT];
__device__ float g_fnorm[KTOT], g_lam[KTOT];
__constant__ int KOFF[5] = {0, 4, 14, 34, 69};

__device__ int   d_seg[NATOM + 1];
__device__ float d_emb[NATOM * EMBD];
__device__ float d_feat[NATOM * FDIM];
__device__ float d_h1pre[NATOM * 256];
__device__ float d_h1[NATOM * 256];
__device__ float d_h2[NATOM * 128];
__device__ __nv_bfloat16 d_Bt_hi[256 * KTOTAL];
__device__ __nv_bfloat16 d_Bt_lo[256 * KTOTAL];

__device__ __forceinline__ float silu_f(float x) { return x / (1.f + expf(-x)); }

__device__ __forceinline__ float powi(float b, int l) {
    float r = 1.f;
#pragma unroll
    for (int i = 0; i < 4; i++) if (i < l) r *= b;
    return r;
}

// bf16 mma.sync (sm_80+ feature set; legacy HMMA pipe on Blackwell)
__device__ __forceinline__ void mma16816(float* c, const uint32_t* a, const uint32_t* b) {
    asm volatile(
        "mma.sync.aligned.m16n8k16.row.col.f32.bf16.bf16.f32 "
        "{%0,%1,%2,%3}, {%4,%5,%6,%7}, {%8,%9}, {%0,%1,%2,%3};"
        : "+f"(c[0]), "+f"(c[1]), "+f"(c[2]), "+f"(c[3])
        : "r"(a[0]), "r"(a[1]), "r"(a[2]), "r"(a[3]), "r"(b[0]), "r"(b[1]));
}

// ---------------- table init ----------------
__global__ void init_tables() {
    if (threadIdx.x == 0 && blockIdx.x == 0) {
        const int fact[5] = {1, 1, 2, 6, 24};
        int idx = 0;
        for (int iz = 0; iz < 4; iz++) {
            int z = iz + 1;
            for (int n = 0; n <= z; n++)
                for (int lx = 0; lx <= n; lx++)
                    for (int ly = 0; ly <= n - lx; ly++) {
                        int lz = n - lx - ly;
                        g_lx[idx] = lx; g_ly[idx] = ly; g_lz[idx] = lz;
                        g_izk[idx] = iz;
                        g_fnorm[idx] = (float)fact[z] /
                            (float)(fact[z - n] * fact[lx] * fact[ly] * fact[lz]);
                        g_lam[idx] = (n & 1) ? -1.f : 1.f;
                        idx++;
                    }
        }
    }
}

// ---------------- segment offsets ----------------
__global__ void seg_kernel(const int* __restrict__ fia) {
    int a = blockIdx.x * blockDim.x + threadIdx.x;
    if (a <= NATOM) {
        int lo = 0, hi = NEDGE;
        while (lo < hi) {
            int mid = (lo + hi) >> 1;
            if (fia[mid] < a) lo = mid + 1; else hi = mid;
        }
        d_seg[a] = lo;
    }
}

// ---------------- per-atom feature kernel (unchanged, known-good) ----------------
__global__ __launch_bounds__(256, 3) void feature_kernel(
    const float* __restrict__ rij,
    const float* __restrict__ Wr1, const float* __restrict__ br1,
    const float* __restrict__ Wr2, const float* __restrict__ br2,
    const float* __restrict__ Ws1, const float* __restrict__ bs1,
    const float* __restrict__ Ws2, const float* __restrict__ bs2,
    const int* __restrict__ species)
{
    extern __shared__ float sm[];
    float* Wr1s = sm;
    float* br1s = Wr1s + NRADB * 64;
    float* Wr2s = br1s + 64;
    float* br2s = Wr2s + 64 * 120;
    float* rads = br2s + 120;
    float* gvs  = rads + TILE * 120;
    float* gis  = gvs + TILE * 72;
    float* ebuf = gis + NCELL;
    float* hsp  = ebuf + 8 * 88;

    int tid = threadIdx.x;
    int a = blockIdx.x;

    for (int i = tid; i < NRADB * 64; i += 256) Wr1s[i] = Wr1[i];
    if (tid < 64)  br1s[tid] = br1[tid];
    for (int i = tid; i < 64 * 120; i += 256) Wr2s[i] = Wr2[i];
    if (tid < 120) br2s[tid] = br2[tid];

    int sidx = species[a];
    if (tid < 32) hsp[tid] = silu_f(Ws1[sidx * 32 + tid] + bs1[tid]);
    __syncthreads();
    if (tid < EMBD) {
        float acc = bs2[tid];
        for (int i = 0; i < 32; i++) acc += hsp[i] * Ws2[i * EMBD + tid];
        d_emb[a * EMBD + tid] = acc;
    }

    float acc[CPT];
    int radoff[CPT], gvk[CPT];
#pragma unroll
    for (int c = 0; c < CPT; c++) {
        int cell = tid + c * 256;
        acc[c] = 0.f;
        if (cell < NCELL) {
            int r = cell / 70, k = cell % 70;
            if (k < KTOT) { radoff[c] = r * NCOMP + g_izk[k] + 1; gvk[c] = k; }
            else          { radoff[c] = r * NCOMP;                gvk[c] = -1; }
        } else gvk[c] = -2;
    }

    int beg = d_seg[a], end = d_seg[a + 1];
    int wid = tid >> 5, lane = tid & 31;
    float* bas = ebuf + wid * 88;
    float* hh  = bas + 24;

    for (int pos = beg; pos < end; pos += TILE) {
        int nE = min(TILE, end - pos);
        for (int i = 0; i < 4; i++) {
            int slot = wid * 4 + i;
            if (slot < nE) {
                int e = pos + slot;
                float x = rij[e * 3], y = rij[e * 3 + 1], z = rij[e * 3 + 2];
                float r = sqrtf(x * x + y * y + z * z);
                float inv = 1.f / r;
                float ux = x * inv + 1e-12f;
                float uy = y * inv + 1e-12f;
                float uz = z * inv + 1e-12f;
                float rc = fminf(r, 6.f);
                float fcv = 0.5f * (cosf(rc * 0.52359877559829887f) + 1.f);
                if (lane < NRADB) {
                    float d = r - (6.f / 23.f) * (float)lane;
                    bas[lane] = expf(-8.f * d * d) * fcv;
                }
                __syncwarp();
#pragma unroll
                for (int q = 0; q < 2; q++) {
                    int j = lane + q * 32;
                    float s = br1s[j];
#pragma unroll
                    for (int k = 0; k < NRADB; k++) s += bas[k] * Wr1s[k * 64 + j];
                    hh[j] = silu_f(s);
                }
                __syncwarp();
#pragma unroll
                for (int q = 0; q < 4; q++) {
                    int j = lane + q * 32;
                    if (j < 120) {
                        float s = br2s[j];
#pragma unroll 8
                        for (int k = 0; k < 64; k++) s += hh[k] * Wr2s[k * 120 + j];
                        rads[slot * 120 + j] = silu_f(s);
                    }
                }
#pragma unroll
                for (int q = 0; q < 3; q++) {
                    int k = lane + q * 32;
                    if (k < KTOT) {
                        gvs[slot * 72 + k] = g_fnorm[k] *
                            powi(ux, g_lx[k]) * powi(uy, g_ly[k]) * powi(uz, g_lz[k]);
                    }
                }
            }
        }
        __syncthreads();
#pragma unroll
        for (int c = 0; c < CPT; c++) {
            if (gvk[c] == -2) continue;
            int ro = radoff[c];
            float aa = acc[c];
            if (gvk[c] >= 0) {
                int gk = gvk[c];
                for (int e = 0; e < nE; e++) aa += rads[e * 120 + ro] * gvs[e * 72 + gk];
            } else {
                for (int e = 0; e < nE; e++) aa += rads[e * 120 + ro];
            }
            acc[c] = aa;
        }
        __syncthreads();
    }

#pragma unroll
    for (int c = 0; c < CPT; c++) {
        int cell = tid + c * 256;
        if (cell < NCELL) gis[cell] = acc[c];
    }
    __syncthreads();

    if (tid < FDIM) {
        int grp = tid / NRADB, r = tid % NRADB;
        float v;
        if (grp == 0) {
            v = gis[r * 70 + KTOT];
        } else {
            int iz = (grp - 1) >> 1;
            int neg = (grp - 1) & 1;
            float ssum = 0.f;
            for (int k = KOFF[iz]; k < KOFF[iz + 1]; k++) {
                float g = gis[r * 70 + k];
                ssum += g * g * (neg ? g_lam[k] : 1.f);
            }
            v = ssum * (1.0f / (float)(1 << iz));
        }
        d_feat[a * FDIM + tid] = v;
    }
}

// ---------------- Wa1 -> transposed bf16 hi/lo [256][3456] ----------------
__global__ void conv_w1_kernel(const float* __restrict__ Wa1) {
    __shared__ float t[32][33];
    int k0 = blockIdx.x * 32, n0 = blockIdx.y * 32;
    int tx = threadIdx.x, ty = threadIdx.y;   // 32 x 8
#pragma unroll
    for (int r = 0; r < 32; r += 8)
        t[ty + r][tx] = Wa1[(size_t)(k0 + ty + r) * 256 + n0 + tx];
    __syncthreads();
#pragma unroll
    for (int r = 0; r < 32; r += 8) {
        int n = n0 + ty + r, k = k0 + tx;
        float v = t[tx][ty + r];
        __nv_bfloat16 h = __float2bfloat16(v);
        d_Bt_hi[(size_t)n * KTOTAL + k] = h;
        d_Bt_lo[(size_t)n * KTOTAL + k] = __float2bfloat16(v - __bfloat162float(h));
    }
}

__global__ void zero_h1pre_kernel() {
    int i = blockIdx.x * blockDim.x + threadIdx.x;
    ((float4*)d_h1pre)[i] = make_float4(0.f, 0.f, 0.f, 0.f);
}

// ---------------- GEMM1 via mma.sync bf16 3-pass split ----------------
// h1pre += X @ Wa1 where X[a][k] = feat[a][k>>4] * emb[a][k&15] (generated on the fly).
// BM=128, BN=64, BK=32; 8 warps (4x2), warp tile 32x32; split-K over blockIdx.z.
#define LDA 40   // bf16 elems per A smem row (pad 32->40: conflict-free fragment loads)
#define LDB 40
__global__ __launch_bounds__(256) void gemm1_mma_kernel(
    const float* __restrict__ feat, const float* __restrict__ emb,
    const __nv_bfloat16* __restrict__ Bth, const __nv_bfloat16* __restrict__ Btl,
    float* __restrict__ outp)
{
    __shared__ __nv_bfloat16 sAh[128 * LDA], sAl[128 * LDA];
    __shared__ __nv_bfloat16 sBh[64 * LDB],  sBl[64 * LDB];

    int tid = threadIdx.x;
    int warp = tid >> 5, lane = tid & 31;
    int gid = lane >> 2, tig = lane & 3;
    int wm0 = (warp >> 1) * 32, wn0 = (warp & 1) * 32;
    int mtile = blockIdx.x, ntile = blockIdx.y, kseg = blockIdx.z;

    // A-generation assignment: thread handles row m, k-halves of each 32-chunk
    int m = tid >> 1, half = tid & 1;
    int gm = mtile * 128 + m;
    float ev[16];
    {
        const float4* ep = (const float4*)(emb + gm * 16);
        float4 a0 = ep[0], a1 = ep[1], a2 = ep[2], a3 = ep[3];
        ev[0] = a0.x; ev[1] = a0.y; ev[2] = a0.z; ev[3] = a0.w;
        ev[4] = a1.x; ev[5] = a1.y; ev[6] = a1.z; ev[7] = a1.w;
        ev[8] = a2.x; ev[9] = a2.y; ev[10] = a2.z; ev[11] = a2.w;
        ev[12] = a3.x; ev[13] = a3.y; ev[14] = a3.z; ev[15] = a3.w;
    }
    const float* fr = feat + (size_t)gm * FDIM;
    int brow = tid >> 2, bq = tid & 3;

    float acc[2][4][4];
#pragma unroll
    for (int i = 0; i < 2; i++)
#pragma unroll
        for (int j = 0; j < 4; j++)
#pragma unroll
            for (int q = 0; q < 4; q++) acc[i][j][q] = 0.f;

    for (int it = 0; it < ITERS; it++) {
        int k0 = (kseg * ITERS + it) * 32;
        __syncthreads();   // previous iter's fragment reads done before overwrite
        // ---- A tiles: on-the-fly feat x emb, bf16 hi/lo split ----
        {
            int kb = k0 + half * 16;         // 16-aligned: one feat value per half
            float f0 = fr[kb >> 4];
#pragma unroll
            for (int j = 0; j < 16; j += 2) {
                float v0 = f0 * ev[j];
                float v1 = f0 * ev[j + 1];
                __nv_bfloat16 h0 = __float2bfloat16(v0);
                __nv_bfloat16 h1 = __float2bfloat16(v1);
                __nv_bfloat16 l0 = __float2bfloat16(v0 - __bfloat162float(h0));
                __nv_bfloat16 l1 = __float2bfloat16(v1 - __bfloat162float(h1));
                int o = m * LDA + half * 16 + j;
                *(__nv_bfloat162*)&sAh[o] = __halves2bfloat162(h0, h1);
                *(__nv_bfloat162*)&sAl[o] = __halves2bfloat162(l0, l1);
            }
        }
        // ---- B tiles: 64 rows x 32 k, uint4 loads ----
        {
            size_t off = (size_t)(ntile * 64 + brow) * KTOTAL + k0 + bq * 8;
            *(uint4*)&sBh[brow * LDB + bq * 8] = *(const uint4*)(Bth + off);
            *(uint4*)&sBl[brow * LDB + bq * 8] = *(const uint4*)(Btl + off);
        }
        __syncthreads();
        // ---- 2 k-steps of m16n8k16 ----
#pragma unroll
        for (int kk = 0; kk < 2; kk++) {
            int kf = kk * 16 + tig * 2;
            uint32_t ah[2][4], al[2][4], bh[4][2], bl[4][2];
#pragma unroll
            for (int i = 0; i < 2; i++) {
                int r = wm0 + i * 16 + gid;
                ah[i][0] = *(const uint32_t*)&sAh[r * LDA + kf];
                ah[i][1] = *(const uint32_t*)&sAh[(r + 8) * LDA + kf];
                ah[i][2] = *(const uint32_t*)&sAh[r * LDA + kf + 8];
                ah[i][3] = *(const uint32_t*)&sAh[(r + 8) * LDA + kf + 8];
                al[i][0] = *(const uint32_t*)&sAl[r * LDA + kf];
                al[i][1] = *(const uint32_t*)&sAl[(r + 8) * LDA + kf];
                al[i][2] = *(const uint32_t*)&sAl[r * LDA + kf + 8];
                al[i][3] = *(const uint32_t*)&sAl[(r + 8) * LDA + kf + 8];
            }
#pragma unroll
            for (int j = 0; j < 4; j++) {
                int n = wn0 + j * 8 + gid;
                bh[j][0] = *(const uint32_t*)&sBh[n * LDB + kf];
                bh[j][1] = *(const uint32_t*)&sBh[n * LDB + kf + 8];
                bl[j][0] = *(const uint32_t*)&sBl[n * LDB + kf];
                bl[j][1] = *(const uint32_t*)&sBl[n * LDB + kf + 8];
            }
#pragma unroll
            for (int i = 0; i < 2; i++)
#pragma unroll
                for (int j = 0; j < 4; j++) {
                    mma16816(acc[i][j], ah[i], bh[j]);
                    mma16816(acc[i][j], al[i], bh[j]);
                    mma16816(acc[i][j], ah[i], bl[j]);
                }
        }
    }

    // ---- epilogue: split-K partials via atomicAdd ----
#pragma unroll
    for (int i = 0; i < 2; i++) {
        int r0 = mtile * 128 + wm0 + i * 16 + gid;
#pragma unroll
        for (int j = 0; j < 4; j++) {
            int cn = ntile * 64 + wn0 + j * 8 + tig * 2;
            atomicAdd(outp + (size_t)r0 * 256 + cn,       acc[i][j][0]);
            atomicAdd(outp + (size_t)r0 * 256 + cn + 1,   acc[i][j][1]);
            atomicAdd(outp + (size_t)(r0 + 8) * 256 + cn,     acc[i][j][2]);
            atomicAdd(outp + (size_t)(r0 + 8) * 256 + cn + 1, acc[i][j][3]);
        }
    }
}

__global__ void bias_silu_kernel(const float* __restrict__ ba1) {
    int i = blockIdx.x * blockDim.x + threadIdx.x;
    d_h1[i] = silu_f(d_h1pre[i] + ba1[i & 255]);
}

// ---------------- fp32 GEMM2 + bias + silu ----------------
__global__ __launch_bounds__(256) void gemm_silu_k(
    const float* __restrict__ A, const float* __restrict__ B,
    const float* __restrict__ bias, float* __restrict__ C,
    int M, int N, int K)
{
    const int BM = 64, BN = 64, BK = 32;
    __shared__ float As[BK][BM + 1];
    __shared__ float Bs[BK][BN + 1];
    int tid = threadIdx.x;
    int tx = tid % 16, ty = tid / 16;
    int row0 = blockIdx.x * BM, col0 = blockIdx.y * BN;
    float accum[4][4];
#pragma unroll
    for (int i = 0; i < 4; i++)
#pragma unroll
        for (int j = 0; j < 4; j++) accum[i][j] = 0.f;

    for (int k0 = 0; k0 < K; k0 += BK) {
        for (int i = tid; i < BM * BK; i += 256) {
            int m = i / BK, k = i % BK;
            As[k][m] = A[(size_t)(row0 + m) * K + k0 + k];
        }
        for (int i = tid; i < BK * BN; i += 256) {
            int k = i / BN, n = i % BN;
            Bs[k][n] = B[(size_t)(k0 + k) * N + col0 + n];
        }
        __syncthreads();
#pragma unroll
        for (int k = 0; k < BK; k++) {
            float av[4], bv[4];
#pragma unroll
            for (int i = 0; i < 4; i++) av[i] = As[k][ty * 4 + i];
#pragma unroll
            for (int j = 0; j < 4; j++) bv[j] = Bs[k][tx * 4 + j];
#pragma unroll
            for (int i = 0; i < 4; i++)
#pragma unroll
                for (int j = 0; j < 4; j++) accum[i][j] += av[i] * bv[j];
        }
        __syncthreads();
    }
#pragma unroll
    for (int i = 0; i < 4; i++) {
        int row = row0 + ty * 4 + i;
#pragma unroll
        for (int j = 0; j < 4; j++) {
            int col = col0 + tx * 4 + j;
            C[(size_t)row * N + col] = silu_f(accum[i][j] + bias[col]);
        }
    }
}

// ---------------- final reduction ----------------
__global__ void zero_out_k(float* out) { out[0] = 0.f; }

__global__ void final_kernel(const float* __restrict__ Wa3,
                             const float* __restrict__ ba3, float* out) {
    int gt = blockIdx.x * blockDim.x + threadIdx.x;
    int a = gt >> 5, lane = gt & 31;
    if (a < NATOM) {
        float s = 0.f;
#pragma unroll
        for (int i = lane; i < 128; i += 32) s += d_h2[a * 128 + i] * Wa3[i];
#pragma unroll
        for (int o = 16; o; o >>= 1) s += __shfl_xor_sync(0xffffffffu, s, o);
        if (lane == 0) atomicAdd(out, s + ba3[0]);
    }
}

// ---------------- launch ----------------
extern "C" void kernel_launch(void* const* d_in, const int* in_sizes, int n_in,
                              void* d_out, int out_size) {
    (void)in_sizes; (void)n_in; (void)out_size;
    const float* rij = (const float*)d_in[0];
    const float* Wr1 = (const float*)d_in[1];
    const float* br1 = (const float*)d_in[2];
    const float* Wr2 = (const float*)d_in[3];
    const float* br2 = (const float*)d_in[4];
    const float* Ws1 = (const float*)d_in[5];
    const float* bs1 = (const float*)d_in[6];
    const float* Ws2 = (const float*)d_in[7];
    const float* bs2 = (const float*)d_in[8];
    const float* Wa1 = (const float*)d_in[9];
    const float* ba1 = (const float*)d_in[10];
    const float* Wa2 = (const float*)d_in[11];
    const float* ba2 = (const float*)d_in[12];
    const float* Wa3 = (const float*)d_in[13];
    const float* ba3 = (const float*)d_in[14];
    const int*   fia     = (const int*)d_in[15];
    const int*   species = (const int*)d_in[16];
    float* out = (float*)d_out;

    void *p_feat, *p_emb, *p_h1pre, *p_h1, *p_h2, *p_bth, *p_btl;
    cudaGetSymbolAddress(&p_feat,  d_feat);
    cudaGetSymbolAddress(&p_emb,   d_emb);
    cudaGetSymbolAddress(&p_h1pre, d_h1pre);
    cudaGetSymbolAddress(&p_h1,    d_h1);
    cudaGetSymbolAddress(&p_h2,    d_h2);
    cudaGetSymbolAddress(&p_bth,   d_Bt_hi);
    cudaGetSymbolAddress(&p_btl,   d_Bt_lo);

    init_tables<<<1, 1>>>();
    seg_kernel<<<(NATOM + 1 + 255) / 256, 256>>>(fia);
    conv_w1_kernel<<<dim3(KTOTAL / 32, 256 / 32), dim3(32, 8)>>>(Wa1);
    zero_h1pre_kernel<<<(NATOM * 256 / 4) / 256, 256>>>();

    const int SMEMB = (1536 + 64 + 7680 + 120 + TILE * 120 + TILE * 72 + NCELL + 8 * 88 + 32) * 4;
    cudaFuncSetAttribute(feature_kernel, cudaFuncAttributeMaxDynamicSharedMemorySize, SMEMB);
    feature_kernel<<<NATOM, 256, SMEMB>>>(rij, Wr1, br1, Wr2, br2,
                                          Ws1, bs1, Ws2, bs2, species);

    gemm1_mma_kernel<<<dim3(NATOM / 128, 256 / 64, KSPLIT), 256>>>(
        (const float*)p_feat, (const float*)p_emb,
        (const __nv_bfloat16*)p_bth, (const __nv_bfloat16*)p_btl,
        (float*)p_h1pre);

    bias_silu_kernel<<<NATOM * 256 / 256, 256>>>(ba1);

    gemm_silu_k<<<dim3(NATOM / 64, 128 / 64), 256>>>(
        (const float*)p_h1, Wa2, ba2, (float*)p_h2, NATOM, 128, 256);

    zero_out_k<<<1, 1>>>(out);
    final_kernel<<<NATOM * 32 / 256, 256>>>(Wa3, ba3, out);
}

// round 5
// speedup vs baseline: 2.0339x; 1.2266x over previous
#include <cuda_runtime.h>
#include <cuda_bf16.h>
#include <math.h>
#include <cstdint>

#define NEDGE 65536
#define NATOM 2048
#define NRADB 24
#define NCOMP 5
#define KTOT  69
#define FDIM  216            // 24 * 9
#define EMBD  16
#define TILE  32
#define KTOTAL 3456          // FDIM * EMBD
#define KSPLIT 4
#define ITERS  27            // KTOTAL / KSPLIT / 32

// ---------------- scratch (static device globals) ----------------
__device__ int   g_lx[KTOT], g_ly[KTOT], g_lz[KTOT], g_izk[KTOT];
__device__ float g_fnorm[KTOT], g_lam[KTOT];
__constant__ int KOFF[5] = {0, 4, 14, 34, 69};

__device__ int   d_seg[NATOM + 1];
__device__ float d_emb[NATOM * EMBD];
__device__ float d_feat[NATOM * FDIM];
__device__ float d_h1pre[NATOM * 256];
__device__ float d_h1[NATOM * 256];
__device__ float d_h2[NATOM * 128];
__device__ __nv_bfloat16 d_Bt_hi[256 * KTOTAL];
__device__ __nv_bfloat16 d_Bt_lo[256 * KTOTAL];
__device__ __nv_bfloat16 d_Xh[NATOM * KTOTAL];
__device__ __nv_bfloat16 d_Xl[NATOM * KTOTAL];

__device__ __forceinline__ float silu_f(float x) { return x / (1.f + expf(-x)); }

__device__ __forceinline__ float powi(float b, int l) {
    float r = 1.f;
#pragma unroll
    for (int i = 0; i < 4; i++) if (i < l) r *= b;
    return r;
}

// bf16 mma.sync (family-portable; legacy HMMA pipe on Blackwell)
__device__ __forceinline__ void mma16816(float* c, const uint32_t* a, const uint32_t* b) {
    asm volatile(
        "mma.sync.aligned.m16n8k16.row.col.f32.bf16.bf16.f32 "
        "{%0,%1,%2,%3}, {%4,%5,%6,%7}, {%8,%9}, {%0,%1,%2,%3};"
        : "+f"(c[0]), "+f"(c[1]), "+f"(c[2]), "+f"(c[3])
        : "r"(a[0]), "r"(a[1]), "r"(a[2]), "r"(a[3]), "r"(b[0]), "r"(b[1]));
}

__device__ __forceinline__ void ldsm4(uint32_t* r, uint32_t addr) {
    asm volatile("ldmatrix.sync.aligned.m8n8.x4.shared.b16 {%0,%1,%2,%3}, [%4];"
                 : "=r"(r[0]), "=r"(r[1]), "=r"(r[2]), "=r"(r[3]) : "r"(addr));
}

__device__ __forceinline__ uint32_t smem_u32(const void* p) {
    uint32_t a;
    asm("{ .reg .u64 t; cvta.to.shared.u64 t, %1; cvt.u32.u64 %0, t; }" : "=r"(a) : "l"(p));
    return a;
}

// ---------------- table init ----------------
__global__ void init_tables() {
    if (threadIdx.x == 0 && blockIdx.x == 0) {
        const int fact[5] = {1, 1, 2, 6, 24};
        int idx = 0;
        for (int iz = 0; iz < 4; iz++) {
            int z = iz + 1;
            for (int n = 0; n <= z; n++)
                for (int lx = 0; lx <= n; lx++)
                    for (int ly = 0; ly <= n - lx; ly++) {
                        int lz = n - lx - ly;
                        g_lx[idx] = lx; g_ly[idx] = ly; g_lz[idx] = lz;
                        g_izk[idx] = iz;
                        g_fnorm[idx] = (float)fact[z] /
                            (float)(fact[z - n] * fact[lx] * fact[ly] * fact[lz]);
                        g_lam[idx] = (n & 1) ? -1.f : 1.f;
                        idx++;
                    }
        }
    }
}

// ---------------- segment offsets ----------------
__global__ void seg_kernel(const int* __restrict__ fia) {
    int a = blockIdx.x * blockDim.x + threadIdx.x;
    if (a <= NATOM) {
        int lo = 0, hi = NEDGE;
        while (lo < hi) {
            int mid = (lo + hi) >> 1;
            if (fia[mid] < a) lo = mid + 1; else hi = mid;
        }
        d_seg[a] = lo;
    }
}

// ---------------- per-atom feature kernel ----------------
// Radial layout PERMUTED to [comp][r] (j' = c*24 + r): enables float4 loads everywhere.
__global__ __launch_bounds__(256, 2) void feature_kernel(
    const float* __restrict__ rij,
    const float* __restrict__ Wr1, const float* __restrict__ br1,
    const float* __restrict__ Wr2, const float* __restrict__ br2,
    const float* __restrict__ Ws1, const float* __restrict__ bs1,
    const float* __restrict__ Ws2, const float* __restrict__ bs2,
    const int* __restrict__ species)
{
    extern __shared__ float sm[];
    float* Wr1s = sm;                       // 1536
    float* br1s = Wr1s + NRADB * 64;        // 64
    float* Wr2s = br1s + 64;                // 7680 (columns permuted)
    float* br2s = Wr2s + 64 * 120;          // 120 (permuted)
    float* rads = br2s + 120;               // 32*120 (layout [e][c*24+r])
    float* gvs  = rads + TILE * 120;        // 32*70
    float* gis  = gvs + TILE * 70;          // 70*24 (layout [k][r])
    float* ebuf = gis + 70 * 24;            // 8 * 280 (per warp: bas 24 + hh 4*64)
    float* hsp  = ebuf + 8 * 280;           // 32
    int*   slk  = (int*)(hsp + 32);         // 69 packed lx|ly|lz
    float* sfn  = (float*)(slk + KTOT);     // 69

    int tid = threadIdx.x;
    int a = blockIdx.x;

    for (int i = tid; i < NRADB * 64; i += 256) Wr1s[i] = Wr1[i];
    if (tid < 64)  br1s[tid] = br1[tid];
    for (int i = tid; i < 64 * 120; i += 256) {
        int k = i / 120, j = i % 120;
        Wr2s[k * 120 + (j % 5) * 24 + j / 5] = Wr2[i];
    }
    if (tid < 120) br2s[(tid % 5) * 24 + tid / 5] = br2[tid];
    if (tid < KTOT) {
        slk[tid] = g_lx[tid] | (g_ly[tid] << 8) | (g_lz[tid] << 16);
        sfn[tid] = g_fnorm[tid];
    }

    int sidx = species[a];
    if (tid < 32) hsp[tid] = silu_f(Ws1[sidx * 32 + tid] + bs1[tid]);
    __syncthreads();
    if (tid < EMBD) {
        float acc = bs2[tid];
        for (int i = 0; i < 32; i++) acc += hsp[i] * Ws2[i * EMBD + tid];
        d_emb[a * EMBD + tid] = acc;
    }

    int beg = d_seg[a], end = d_seg[a + 1];
    int wid = tid >> 5, lane = tid & 31;
    float* bas = ebuf + wid * 280;
    float* hhw = bas + 24;                  // [4 edges][64]

    // phase-B ownership: thread < 210 owns (k = tid/3, r0 = (tid%3)*8), 8 accumulators
    bool actB = tid < 210;
    int kB = tid / 3, r0B = (tid % 3) * 8, cB = 0;
    if (actB) cB = (kB < 4) ? 1 : (kB < 14) ? 2 : (kB < 34) ? 3 : (kB < 69) ? 4 : 0;
    float accB[8];
#pragma unroll
    for (int q = 0; q < 8; q++) accB[q] = 0.f;

    for (int pos = beg; pos < end; pos += TILE) {
        int nE = min(TILE, end - pos);
        // ---- per-edge basis + MLP1 + angular (serial over warp's 4 edges) ----
        for (int i = 0; i < 4; i++) {
            int slot = wid * 4 + i;
            bool act = slot < nE;
            if (act) {
                int e = pos + slot;
                float x = rij[e * 3], y = rij[e * 3 + 1], z = rij[e * 3 + 2];
                float r = sqrtf(x * x + y * y + z * z);
                float inv = 1.f / r;
                float ux = x * inv + 1e-12f;
                float uy = y * inv + 1e-12f;
                float uz = z * inv + 1e-12f;
                float rc = fminf(r, 6.f);
                float fcv = 0.5f * (cosf(rc * 0.52359877559829887f) + 1.f);
                if (lane < NRADB) {
                    float d = r - (6.f / 23.f) * (float)lane;
                    bas[lane] = expf(-8.f * d * d) * fcv;
                }
                __syncwarp();
#pragma unroll
                for (int q = 0; q < 2; q++) {
                    int j = lane + q * 32;
                    float s = br1s[j];
#pragma unroll
                    for (int k = 0; k < NRADB; k++) s += bas[k] * Wr1s[k * 64 + j];
                    hhw[i * 64 + j] = silu_f(s);
                }
#pragma unroll
                for (int q = 0; q < 3; q++) {
                    int k = lane + q * 32;
                    if (k < KTOT) {
                        int pk = slk[k];
                        gvs[slot * 70 + k] = sfn[k] *
                            powi(ux, pk & 255) * powi(uy, (pk >> 8) & 255) * powi(uz, pk >> 16);
                    }
                }
            } else {
                __syncwarp();
            }
            __syncwarp();
        }
        // ---- joint MLP2 for the warp's 4 edges: lane -> 4 outputs ----
        if (lane < 30) {
            int j0 = lane * 4;
            float ac[4][4];
#pragma unroll
            for (int e = 0; e < 4; e++)
#pragma unroll
                for (int q = 0; q < 4; q++) ac[e][q] = 0.f;
#pragma unroll 8
            for (int k = 0; k < 64; k++) {
                float4 w = *(const float4*)&Wr2s[k * 120 + j0];
                float h0 = hhw[k], h1 = hhw[64 + k], h2 = hhw[128 + k], h3 = hhw[192 + k];
                ac[0][0] += h0 * w.x; ac[0][1] += h0 * w.y; ac[0][2] += h0 * w.z; ac[0][3] += h0 * w.w;
                ac[1][0] += h1 * w.x; ac[1][1] += h1 * w.y; ac[1][2] += h1 * w.z; ac[1][3] += h1 * w.w;
                ac[2][0] += h2 * w.x; ac[2][1] += h2 * w.y; ac[2][2] += h2 * w.z; ac[2][3] += h2 * w.w;
                ac[3][0] += h3 * w.x; ac[3][1] += h3 * w.y; ac[3][2] += h3 * w.z; ac[3][3] += h3 * w.w;
            }
            float4 bb = *(const float4*)&br2s[j0];
#pragma unroll
            for (int e = 0; e < 4; e++) {
                int slot = wid * 4 + e;
                if (slot < nE) {
                    float4 o;
                    o.x = silu_f(ac[e][0] + bb.x);
                    o.y = silu_f(ac[e][1] + bb.y);
                    o.z = silu_f(ac[e][2] + bb.z);
                    o.w = silu_f(ac[e][3] + bb.w);
                    *(float4*)&rads[slot * 120 + j0] = o;
                }
            }
        }
        __syncthreads();
        // ---- phase B: register accumulation, float4 radial loads ----
        if (actB) {
            int base = cB * 24 + r0B;
            for (int e = 0; e < nE; e++) {
                float g = (kB < KTOT) ? gvs[e * 70 + kB] : 1.f;
                const float4* rp = (const float4*)&rads[e * 120 + base];
                float4 p0 = rp[0], p1 = rp[1];
                accB[0] += g * p0.x; accB[1] += g * p0.y;
                accB[2] += g * p0.z; accB[3] += g * p0.w;
                accB[4] += g * p1.x; accB[5] += g * p1.y;
                accB[6] += g * p1.z; accB[7] += g * p1.w;
            }
        }
        __syncthreads();
    }

    if (actB) {
#pragma unroll
        for (int q = 0; q < 8; q++) gis[kB * 24 + r0B + q] = accB[q];
    }
    __syncthreads();

    // features: [feat0 | z1+ z1- | z2+ z2- | z3+ z3- | z4+ z4-], 24 each
    if (tid < FDIM) {
        int grp = tid / NRADB, r = tid % NRADB;
        float v;
        if (grp == 0) {
            v = gis[KTOT * 24 + r];
        } else {
            int iz = (grp - 1) >> 1;
            int neg = (grp - 1) & 1;
            float ssum = 0.f;
            for (int k = KOFF[iz]; k < KOFF[iz + 1]; k++) {
                float g = gis[k * 24 + r];
                ssum += g * g * (neg ? g_lam[k] : 1.f);
            }
            v = ssum * (1.0f / (float)(1 << iz));
        }
        d_feat[a * FDIM + tid] = v;
    }
}

// ---------------- Wa1 -> transposed bf16 hi/lo [256][3456] ----------------
__global__ void conv_w1_kernel(const float* __restrict__ Wa1) {
    __shared__ float t[32][33];
    int k0 = blockIdx.x * 32, n0 = blockIdx.y * 32;
    int tx = threadIdx.x, ty = threadIdx.y;   // 32 x 8
#pragma unroll
    for (int r = 0; r < 32; r += 8)
        t[ty + r][tx] = Wa1[(size_t)(k0 + ty + r) * 256 + n0 + tx];
    __syncthreads();
#pragma unroll
    for (int r = 0; r < 32; r += 8) {
        int n = n0 + ty + r, k = k0 + tx;
        float v = t[tx][ty + r];
        __nv_bfloat16 h = __float2bfloat16(v);
        d_Bt_hi[(size_t)n * KTOTAL + k] = h;
        d_Bt_lo[(size_t)n * KTOTAL + k] = __float2bfloat16(v - __bfloat162float(h));
    }
}

// ---------------- X = feat (x) emb -> bf16 hi/lo [2048][3456] ----------------
__global__ void xgen_kernel(const float* __restrict__ feat, const float* __restrict__ emb) {
    int t = blockIdx.x * blockDim.x + threadIdx.x;   // NATOM*432 threads, 8 k each
    int a = t / 432, rem = t % 432;
    int k0 = rem * 8;
    float f = feat[a * FDIM + (k0 >> 4)];
    const float4* ep = (const float4*)(emb + a * EMBD + (k0 & 15));
    float4 e0 = ep[0], e1 = ep[1];
    float v[8] = {f * e0.x, f * e0.y, f * e0.z, f * e0.w,
                  f * e1.x, f * e1.y, f * e1.z, f * e1.w};
    uint4 uh, ul;
    uint32_t* ph = (uint32_t*)&uh;
    uint32_t* pl = (uint32_t*)&ul;
#pragma unroll
    for (int i = 0; i < 4; i++) {
        __nv_bfloat16 h0 = __float2bfloat16(v[2 * i]);
        __nv_bfloat16 h1 = __float2bfloat16(v[2 * i + 1]);
        __nv_bfloat162 hh = __halves2bfloat162(h0, h1);
        __nv_bfloat162 ll = __halves2bfloat162(
            __float2bfloat16(v[2 * i] - __bfloat162float(h0)),
            __float2bfloat16(v[2 * i + 1] - __bfloat162float(h1)));
        ph[i] = *(uint32_t*)&hh;
        pl[i] = *(uint32_t*)&ll;
    }
    *(uint4*)&d_Xh[(size_t)a * KTOTAL + k0] = uh;
    *(uint4*)&d_Xl[(size_t)a * KTOTAL + k0] = ul;
}

__global__ void zero_h1pre_kernel() {
    int i = blockIdx.x * blockDim.x + threadIdx.x;
    ((float4*)d_h1pre)[i] = make_float4(0.f, 0.f, 0.f, 0.f);
}

// ---------------- GEMM1: double-buffered ldmatrix mma pipeline ----------------
// h1pre += X @ Wa1 (3-pass bf16 split). BM=128, BN=64, BK=32; 8 warps (4x2), warp 32x32.
#define LDA 40           // row stride 80 B: 16B-aligned, all-32-bank coverage
#define A_HI_O 0
#define A_LO_O 10240
#define B_HI_O 20480
#define B_LO_O 25600
#define SBUF   30720
__global__ __launch_bounds__(256) void gemm1_mma_kernel(
    const __nv_bfloat16* __restrict__ Xh, const __nv_bfloat16* __restrict__ Xl,
    const __nv_bfloat16* __restrict__ Bth, const __nv_bfloat16* __restrict__ Btl,
    float* __restrict__ outp)
{
    extern __shared__ char smem[];
    uint32_t sb = smem_u32(smem);
    int tid = threadIdx.x;
    int warp = tid >> 5, lane = tid & 31;
    int wm0 = (warp >> 1) * 32, wn0 = (warp & 1) * 32;
    int mtile = blockIdx.x, ntile = blockIdx.y, kseg = blockIdx.z;

    // ldmatrix per-lane address offsets
    int lrow = (lane & 7) + ((lane >> 3) & 1) * 8;
    int lcol = (lane >> 4) * 8;

    // load assignments
    int arow = tid >> 1, aq = tid & 1;       // A: row, 16-k half
    int brow = tid >> 2, bq = tid & 3;       // B: row, 8-k quarter
    size_t gA = (size_t)(mtile * 128 + arow) * KTOTAL;
    size_t gB = (size_t)(ntile * 64 + brow) * KTOTAL;

    uint4 vah0, vah1, val0, val1, vbh, vbl;
    auto ldg = [&](int it) {
        int k0 = (kseg * ITERS + it) * 32;
        vah0 = *(const uint4*)(Xh + gA + k0 + aq * 16);
        vah1 = *(const uint4*)(Xh + gA + k0 + aq * 16 + 8);
        val0 = *(const uint4*)(Xl + gA + k0 + aq * 16);
        val1 = *(const uint4*)(Xl + gA + k0 + aq * 16 + 8);
        vbh  = *(const uint4*)(Bth + gB + k0 + bq * 8);
        vbl  = *(const uint4*)(Btl + gB + k0 + bq * 8);
    };
    auto sts = [&](int buf) {
        char* base = smem + buf * SBUF;
        int ao = arow * 80 + aq * 32;
        *(uint4*)(base + A_HI_O + ao)      = vah0;
        *(uint4*)(base + A_HI_O + ao + 16) = vah1;
        *(uint4*)(base + A_LO_O + ao)      = val0;
        *(uint4*)(base + A_LO_O + ao + 16) = val1;
        int bo = brow * 80 + bq * 16;
        *(uint4*)(base + B_HI_O + bo) = vbh;
        *(uint4*)(base + B_LO_O + bo) = vbl;
    };

    float acc[2][4][4];
#pragma unroll
    for (int i = 0; i < 2; i++)
#pragma unroll
        for (int j = 0; j < 4; j++)
#pragma unroll
            for (int q = 0; q < 4; q++) acc[i][j][q] = 0.f;

    ldg(0);
    sts(0);
    __syncthreads();

    for (int it = 0; it < ITERS; it++) {
        int buf = it & 1;
        bool more = (it + 1) < ITERS;
        if (more) ldg(it + 1);
        uint32_t aH = sb + buf * SBUF + A_HI_O;
        uint32_t aL = sb + buf * SBUF + A_LO_O;
        uint32_t bH = sb + buf * SBUF + B_HI_O;
        uint32_t bL = sb + buf * SBUF + B_LO_O;
#pragma unroll
        for (int kk = 0; kk < 2; kk++) {
            int kcol = kk * 16 + lcol;
            uint32_t ah[2][4], al[2][4], bh[4][2], bl[4][2];
#pragma unroll
            for (int i = 0; i < 2; i++) {
                uint32_t off = (uint32_t)(((wm0 + i * 16 + lrow) * LDA + kcol) * 2);
                ldsm4(ah[i], aH + off);
                ldsm4(al[i], aL + off);
            }
#pragma unroll
            for (int j2 = 0; j2 < 2; j2++) {
                uint32_t off = (uint32_t)(((wn0 + j2 * 16 + lrow) * LDA + kcol) * 2);
                uint32_t t[4];
                ldsm4(t, bH + off);
                bh[2 * j2][0] = t[0]; bh[2 * j2 + 1][0] = t[1];
                bh[2 * j2][1] = t[2]; bh[2 * j2 + 1][1] = t[3];
                ldsm4(t, bL + off);
                bl[2 * j2][0] = t[0]; bl[2 * j2 + 1][0] = t[1];
                bl[2 * j2][1] = t[2]; bl[2 * j2 + 1][1] = t[3];
            }
#pragma unroll
            for (int i = 0; i < 2; i++)
#pragma unroll
                for (int j = 0; j < 4; j++) {
                    mma16816(acc[i][j], ah[i], bh[j]);
                    mma16816(acc[i][j], al[i], bh[j]);
                    mma16816(acc[i][j], ah[i], bl[j]);
                }
        }
        if (more) sts(buf ^ 1);
        __syncthreads();
    }

    // ---- epilogue: split-K partials via atomicAdd ----
    int gid = lane >> 2, tig = lane & 3;
#pragma unroll
    for (int i = 0; i < 2; i++) {
        int r0 = mtile * 128 + wm0 + i * 16 + gid;
#pragma unroll
        for (int j = 0; j < 4; j++) {
            int cn = ntile * 64 + wn0 + j * 8 + tig * 2;
            atomicAdd(outp + (size_t)r0 * 256 + cn,           acc[i][j][0]);
            atomicAdd(outp + (size_t)r0 * 256 + cn + 1,       acc[i][j][1]);
            atomicAdd(outp + (size_t)(r0 + 8) * 256 + cn,     acc[i][j][2]);
            atomicAdd(outp + (size_t)(r0 + 8) * 256 + cn + 1, acc[i][j][3]);
        }
    }
}

__global__ void bias_silu_kernel(const float* __restrict__ ba1) {
    int i = blockIdx.x * blockDim.x + threadIdx.x;
    d_h1[i] = silu_f(d_h1pre[i] + ba1[i & 255]);
}

// ---------------- fp32 GEMM2 + bias + silu ----------------
__global__ __launch_bounds__(256) void gemm_silu_k(
    const float* __restrict__ A, const float* __restrict__ B,
    const float* __restrict__ bias, float* __restrict__ C,
    int M, int N, int K)
{
    const int BM = 64, BN = 64, BK = 32;
    __shared__ float As[BK][BM + 1];
    __shared__ float Bs[BK][BN + 1];
    int tid = threadIdx.x;
    int tx = tid % 16, ty = tid / 16;
    int row0 = blockIdx.x * BM, col0 = blockIdx.y * BN;
    float accum[4][4];
#pragma unroll
    for (int i = 0; i < 4; i++)
#pragma unroll
        for (int j = 0; j < 4; j++) accum[i][j] = 0.f;

    for (int k0 = 0; k0 < K; k0 += BK) {
        for (int i = tid; i < BM * BK; i += 256) {
            int m = i / BK, k = i % BK;
            As[k][m] = A[(size_t)(row0 + m) * K + k0 + k];
        }
        for (int i = tid; i < BK * BN; i += 256) {
            int k = i / BN, n = i % BN;
            Bs[k][n] = B[(size_t)(k0 + k) * N + col0 + n];
        }
        __syncthreads();
#pragma unroll
        for (int k = 0; k < BK; k++) {
            float av[4], bv[4];
#pragma unroll
            for (int i = 0; i < 4; i++) av[i] = As[k][ty * 4 + i];
#pragma unroll
            for (int j = 0; j < 4; j++) bv[j] = Bs[k][tx * 4 + j];
#pragma unroll
            for (int i = 0; i < 4; i++)
#pragma unroll
                for (int j = 0; j < 4; j++) accum[i][j] += av[i] * bv[j];
        }
        __syncthreads();
    }
#pragma unroll
    for (int i = 0; i < 4; i++) {
        int row = row0 + ty * 4 + i;
#pragma unroll
        for (int j = 0; j < 4; j++) {
            int col = col0 + tx * 4 + j;
            C[(size_t)row * N + col] = silu_f(accum[i][j] + bias[col]);
        }
    }
}

// ---------------- final reduction ----------------
__global__ void zero_out_k(float* out) { out[0] = 0.f; }

__global__ void final_kernel(const float* __restrict__ Wa3,
                             const float* __restrict__ ba3, float* out) {
    int gt = blockIdx.x * blockDim.x + threadIdx.x;
    int a = gt >> 5, lane = gt & 31;
    if (a < NATOM) {
        float s = 0.f;
#pragma unroll
        for (int i = lane; i < 128; i += 32) s += d_h2[a * 128 + i] * Wa3[i];
#pragma unroll
        for (int o = 16; o; o >>= 1) s += __shfl_xor_sync(0xffffffffu, s, o);
        if (lane == 0) atomicAdd(out, s + ba3[0]);
    }
}

// ---------------- launch ----------------
extern "C" void kernel_launch(void* const* d_in, const int* in_sizes, int n_in,
                              void* d_out, int out_size) {
    (void)in_sizes; (void)n_in; (void)out_size;
    const float* rij = (const float*)d_in[0];
    const float* Wr1 = (const float*)d_in[1];
    const float* br1 = (const float*)d_in[2];
    const float* Wr2 = (const float*)d_in[3];
    const float* br2 = (const float*)d_in[4];
    const float* Ws1 = (const float*)d_in[5];
    const float* bs1 = (const float*)d_in[6];
    const float* Ws2 = (const float*)d_in[7];
    const float* bs2 = (const float*)d_in[8];
    const float* Wa1 = (const float*)d_in[9];
    const float* ba1 = (const float*)d_in[10];
    const float* Wa2 = (const float*)d_in[11];
    const float* ba2 = (const float*)d_in[12];
    const float* Wa3 = (const float*)d_in[13];
    const float* ba3 = (const float*)d_in[14];
    const int*   fia     = (const int*)d_in[15];
    const int*   species = (const int*)d_in[16];
    float* out = (float*)d_out;

    void *p_feat, *p_emb, *p_h1pre, *p_h1, *p_h2, *p_bth, *p_btl, *p_xh, *p_xl;
    cudaGetSymbolAddress(&p_feat,  d_feat);
    cudaGetSymbolAddress(&p_emb,   d_emb);
    cudaGetSymbolAddress(&p_h1pre, d_h1pre);
    cudaGetSymbolAddress(&p_h1,    d_h1);
    cudaGetSymbolAddress(&p_h2,    d_h2);
    cudaGetSymbolAddress(&p_bth,   d_Bt_hi);
    cudaGetSymbolAddress(&p_btl,   d_Bt_lo);
    cudaGetSymbolAddress(&p_xh,    d_Xh);
    cudaGetSymbolAddress(&p_xl,    d_Xl);

    init_tables<<<1, 1>>>();
    seg_kernel<<<(NATOM + 1 + 255) / 256, 256>>>(fia);
    conv_w1_kernel<<<dim3(KTOTAL / 32, 256 / 32), dim3(32, 8)>>>(Wa1);
    zero_h1pre_kernel<<<(NATOM * 256 / 4) / 256, 256>>>();

    // feature smem: 1536+64+7680+120+3840+2240+1680+2240+32 floats + 69 int + 69 float
    const int SMEMB = (1536 + 64 + 7680 + 120 + TILE * 120 + TILE * 70 + 70 * 24 +
                       8 * 280 + 32 + KTOT + KTOT) * 4;
    cudaFuncSetAttribute(feature_kernel, cudaFuncAttributeMaxDynamicSharedMemorySize, SMEMB);
    feature_kernel<<<NATOM, 256, SMEMB>>>(rij, Wr1, br1, Wr2, br2,
                                          Ws1, bs1, Ws2, bs2, species);

    xgen_kernel<<<NATOM * 432 / 256, 256>>>((const float*)p_feat, (const float*)p_emb);

    const int G1SMEM = 2 * SBUF;
    cudaFuncSetAttribute(gemm1_mma_kernel, cudaFuncAttributeMaxDynamicSharedMemorySize, G1SMEM);
    gemm1_mma_kernel<<<dim3(NATOM / 128, 256 / 64, KSPLIT), 256, G1SMEM>>>(
        (const __nv_bfloat16*)p_xh, (const __nv_bfloat16*)p_xl,
        (const __nv_bfloat16*)p_bth, (const __nv_bfloat16*)p_btl,
        (float*)p_h1pre);

    bias_silu_kernel<<<NATOM * 256 / 256, 256>>>(ba1);

    gemm_silu_k<<<dim3(NATOM / 64, 128 / 64), 256>>>(
        (const float*)p_h1, Wa2, ba2, (float*)p_h2, NATOM, 128, 256);

    zero_out_k<<<1, 1>>>(out);
    final_kernel<<<NATOM * 32 / 256, 256>>>(Wa3, ba3, out);
}

// round 6
// speedup vs baseline: 2.1170x; 1.0409x over previous
#include <cuda_runtime.h>
#include <cuda_bf16.h>
#include <math.h>
#include <cstdint>

#define NEDGE 65536
#define NATOM 2048
#define NRADB 24
#define NCOMP 5
#define KTOT  69
#define FDIM  216            // 24 * 9
#define EMBD  16
#define TILE  32
#define KTOTAL 3456          // FDIM * EMBD
#define KSPLIT 4
#define ITERS  27            // KTOTAL / KSPLIT / 32

// ---------------- scratch (static device globals) ----------------
__device__ int   g_lx[KTOT], g_ly[KTOT], g_lz[KTOT], g_izk[KTOT];
__device__ float g_fnorm[KTOT], g_lam[KTOT];
__constant__ int KOFF[5] = {0, 4, 14, 34, 69};

__device__ int   d_seg[NATOM + 1];
__device__ float d_emb[NATOM * EMBD];
__device__ float d_feat[NATOM * FDIM];
__device__ float d_h1parts[KSPLIT * NATOM * 256];
__device__ float d_h1[NATOM * 256];
__device__ float d_h2[NATOM * 128];
__device__ __nv_bfloat16 d_Bt_hi[256 * KTOTAL];
__device__ __nv_bfloat16 d_Bt_lo[256 * KTOTAL];
__device__ __nv_bfloat16 d_Xh[NATOM * KTOTAL];
__device__ __nv_bfloat16 d_Xl[NATOM * KTOTAL];

__device__ __forceinline__ float silu_f(float x) { return x / (1.f + expf(-x)); }

__device__ __forceinline__ float powi(float b, int l) {
    float r = 1.f;
#pragma unroll
    for (int i = 0; i < 4; i++) if (i < l) r *= b;
    return r;
}

// bf16 mma.sync (family-portable; legacy HMMA pipe on Blackwell)
__device__ __forceinline__ void mma16816(float* c, const uint32_t* a, const uint32_t* b) {
    asm volatile(
        "mma.sync.aligned.m16n8k16.row.col.f32.bf16.bf16.f32 "
        "{%0,%1,%2,%3}, {%4,%5,%6,%7}, {%8,%9}, {%0,%1,%2,%3};"
        : "+f"(c[0]), "+f"(c[1]), "+f"(c[2]), "+f"(c[3])
        : "r"(a[0]), "r"(a[1]), "r"(a[2]), "r"(a[3]), "r"(b[0]), "r"(b[1]));
}

__device__ __forceinline__ void ldsm4(uint32_t* r, uint32_t addr) {
    asm volatile("ldmatrix.sync.aligned.m8n8.x4.shared.b16 {%0,%1,%2,%3}, [%4];"
                 : "=r"(r[0]), "=r"(r[1]), "=r"(r[2]), "=r"(r[3]) : "r"(addr));
}

__device__ __forceinline__ uint32_t smem_u32(const void* p) {
    uint32_t a;
    asm("{ .reg .u64 t; cvta.to.shared.u64 t, %1; cvt.u32.u64 %0, t; }" : "=r"(a) : "l"(p));
    return a;
}

// ---------------- table init ----------------
__global__ void init_tables() {
    if (threadIdx.x == 0 && blockIdx.x == 0) {
        const int fact[5] = {1, 1, 2, 6, 24};
        int idx = 0;
        for (int iz = 0; iz < 4; iz++) {
            int z = iz + 1;
            for (int n = 0; n <= z; n++)
                for (int lx = 0; lx <= n; lx++)
                    for (int ly = 0; ly <= n - lx; ly++) {
                        int lz = n - lx - ly;
                        g_lx[idx] = lx; g_ly[idx] = ly; g_lz[idx] = lz;
                        g_izk[idx] = iz;
                        g_fnorm[idx] = (float)fact[z] /
                            (float)(fact[z - n] * fact[lx] * fact[ly] * fact[lz]);
                        g_lam[idx] = (n & 1) ? -1.f : 1.f;
                        idx++;
                    }
        }
    }
}

// ---------------- segment offsets ----------------
__global__ void seg_kernel(const int* __restrict__ fia) {
    int a = blockIdx.x * blockDim.x + threadIdx.x;
    if (a <= NATOM) {
        int lo = 0, hi = NEDGE;
        while (lo < hi) {
            int mid = (lo + hi) >> 1;
            if (fia[mid] < a) lo = mid + 1; else hi = mid;
        }
        d_seg[a] = lo;
    }
}

// ---------------- per-atom feature kernel ----------------
// Radial layout permuted to [comp][r]. Phase A fully joint over the warp's 4 edges:
// geometry on lanes 0-3 (shfl broadcast), basis built by all 32 lanes, MLP1 joint
// (1 LDS.64 weight + 4 broadcast LDS per k for 8 FMA), MLP2 joint (float4 weights).
__global__ __launch_bounds__(256, 2) void feature_kernel(
    const float* __restrict__ rij,
    const float* __restrict__ Wr1, const float* __restrict__ br1,
    const float* __restrict__ Wr2, const float* __restrict__ br2,
    const float* __restrict__ Ws1, const float* __restrict__ bs1,
    const float* __restrict__ Ws2, const float* __restrict__ bs2,
    const int* __restrict__ species)
{
    extern __shared__ float sm[];
    float* Wr1s = sm;                       // 1536 ([k][64])
    float* br1s = Wr1s + NRADB * 64;        // 64
    float* Wr2s = br1s + 64;                // 7680 (columns permuted)
    float* br2s = Wr2s + 64 * 120;          // 120 (permuted)
    float* rads = br2s + 120;               // 32*120 (layout [e][c*24+r])
    float* gvs  = rads + TILE * 120;        // 32*70
    float* gis  = gvs + TILE * 70;          // 70*24 (layout [k][r])
    float* ebuf = gis + 70 * 24;            // 8 * 352 (per warp: bas 4*24 + hh 4*64)
    float* hsp  = ebuf + 8 * 352;           // 32
    int*   slk  = (int*)(hsp + 32);         // 69 packed lx|ly|lz
    float* sfn  = (float*)(slk + KTOT);     // 69

    int tid = threadIdx.x;
    int a = blockIdx.x;

    for (int i = tid; i < NRADB * 64; i += 256) Wr1s[i] = Wr1[i];
    if (tid < 64)  br1s[tid] = br1[tid];
    for (int i = tid; i < 64 * 120; i += 256) {
        int k = i / 120, j = i % 120;
        Wr2s[k * 120 + (j % 5) * 24 + j / 5] = Wr2[i];
    }
    if (tid < 120) br2s[(tid % 5) * 24 + tid / 5] = br2[tid];
    if (tid < KTOT) {
        slk[tid] = g_lx[tid] | (g_ly[tid] << 8) | (g_lz[tid] << 16);
        sfn[tid] = g_fnorm[tid];
    }

    int sidx = species[a];
    if (tid < 32) hsp[tid] = silu_f(Ws1[sidx * 32 + tid] + bs1[tid]);
    __syncthreads();
    if (tid < EMBD) {
        float acc = bs2[tid];
        for (int i = 0; i < 32; i++) acc += hsp[i] * Ws2[i * EMBD + tid];
        d_emb[a * EMBD + tid] = acc;
    }

    int beg = d_seg[a], end = d_seg[a + 1];
    int wid = tid >> 5, lane = tid & 31;
    float* basw = ebuf + wid * 352;         // [4][24]
    float* hhw  = basw + 96;                // [4][64]

    // phase-B ownership: thread < 210 owns (k = tid/3, r0 = (tid%3)*8), 8 accumulators
    bool actB = tid < 210;
    int kB = tid / 3, r0B = (tid % 3) * 8, cB = 0;
    if (actB) cB = (kB < 4) ? 1 : (kB < 14) ? 2 : (kB < 34) ? 3 : (kB < 69) ? 4 : 0;
    float accB[8];
#pragma unroll
    for (int q = 0; q < 8; q++) accB[q] = 0.f;

    for (int pos = beg; pos < end; pos += TILE) {
        int nE = min(TILE, end - pos);
        // ---- geometry: lanes 0-3, one edge each ----
        float rE = 0.f, uxE = 0.f, uyE = 0.f, uzE = 0.f, fcE = 0.f;
        if (lane < 4) {
            int slot = wid * 4 + lane;
            if (slot < nE) {
                int e = pos + slot;
                float x = rij[e * 3], y = rij[e * 3 + 1], z = rij[e * 3 + 2];
                float r = sqrtf(x * x + y * y + z * z);
                float inv = 1.f / r;
                rE = r;
                uxE = x * inv + 1e-12f;
                uyE = y * inv + 1e-12f;
                uzE = z * inv + 1e-12f;
                float rc = fminf(r, 6.f);
                fcE = 0.5f * (cosf(rc * 0.52359877559829887f) + 1.f);
            }
        }
        // ---- basis: all lanes; lane -> edge lane>>3, k = (lane&7)+{0,8,16} ----
        {
            int ge = lane >> 3;
            float rB  = __shfl_sync(0xffffffffu, rE, ge);
            float fcB = __shfl_sync(0xffffffffu, fcE, ge);
#pragma unroll
            for (int q = 0; q < 3; q++) {
                int k = (lane & 7) + q * 8;
                float d = rB - (6.f / 23.f) * (float)k;
                basw[ge * 24 + k] = expf(-8.f * d * d) * fcB;
            }
        }
        __syncwarp();
        // ---- MLP1 joint: lane -> outputs 2*lane, 2*lane+1 for all 4 edges ----
        {
            float a0[4], a1[4];
#pragma unroll
            for (int e = 0; e < 4; e++) { a0[e] = 0.f; a1[e] = 0.f; }
#pragma unroll 6
            for (int k = 0; k < NRADB; k++) {
                float2 w = *(const float2*)&Wr1s[k * 64 + 2 * lane];
                float b0 = basw[k], b1 = basw[24 + k], b2 = basw[48 + k], b3 = basw[72 + k];
                a0[0] += b0 * w.x; a1[0] += b0 * w.y;
                a0[1] += b1 * w.x; a1[1] += b1 * w.y;
                a0[2] += b2 * w.x; a1[2] += b2 * w.y;
                a0[3] += b3 * w.x; a1[3] += b3 * w.y;
            }
            float2 bb = *(const float2*)&br1s[2 * lane];
#pragma unroll
            for (int e = 0; e < 4; e++) {
                hhw[e * 64 + 2 * lane]     = silu_f(a0[e] + bb.x);
                hhw[e * 64 + 2 * lane + 1] = silu_f(a1[e] + bb.y);
            }
        }
        // ---- angular monomials per edge ----
#pragma unroll
        for (int e4 = 0; e4 < 4; e4++) {
            int slot = wid * 4 + e4;
            if (slot < nE) {
                float ux = __shfl_sync(0xffffffffu, uxE, e4);
                float uy = __shfl_sync(0xffffffffu, uyE, e4);
                float uz = __shfl_sync(0xffffffffu, uzE, e4);
#pragma unroll
                for (int q = 0; q < 3; q++) {
                    int k = lane + q * 32;
                    if (k < KTOT) {
                        int pk = slk[k];
                        gvs[slot * 70 + k] = sfn[k] *
                            powi(ux, pk & 255) * powi(uy, (pk >> 8) & 255) * powi(uz, pk >> 16);
                    }
                }
            }
        }
        __syncwarp();
        // ---- MLP2 joint: lane < 30 -> 4 outputs x 4 edges ----
        if (lane < 30) {
            int j0 = lane * 4;
            float ac[4][4];
#pragma unroll
            for (int e = 0; e < 4; e++)
#pragma unroll
                for (int q = 0; q < 4; q++) ac[e][q] = 0.f;
#pragma unroll 8
            for (int k = 0; k < 64; k++) {
                float4 w = *(const float4*)&Wr2s[k * 120 + j0];
                float h0 = hhw[k], h1 = hhw[64 + k], h2 = hhw[128 + k], h3 = hhw[192 + k];
                ac[0][0] += h0 * w.x; ac[0][1] += h0 * w.y; ac[0][2] += h0 * w.z; ac[0][3] += h0 * w.w;
                ac[1][0] += h1 * w.x; ac[1][1] += h1 * w.y; ac[1][2] += h1 * w.z; ac[1][3] += h1 * w.w;
                ac[2][0] += h2 * w.x; ac[2][1] += h2 * w.y; ac[2][2] += h2 * w.z; ac[2][3] += h2 * w.w;
                ac[3][0] += h3 * w.x; ac[3][1] += h3 * w.y; ac[3][2] += h3 * w.z; ac[3][3] += h3 * w.w;
            }
            float4 bb = *(const float4*)&br2s[j0];
#pragma unroll
            for (int e = 0; e < 4; e++) {
                int slot = wid * 4 + e;
                if (slot < nE) {
                    float4 o;
                    o.x = silu_f(ac[e][0] + bb.x);
                    o.y = silu_f(ac[e][1] + bb.y);
                    o.z = silu_f(ac[e][2] + bb.z);
                    o.w = silu_f(ac[e][3] + bb.w);
                    *(float4*)&rads[slot * 120 + j0] = o;
                }
            }
        }
        __syncthreads();
        // ---- phase B: register accumulation, float4 radial loads ----
        if (actB) {
            int base = cB * 24 + r0B;
            for (int e = 0; e < nE; e++) {
                float g = (kB < KTOT) ? gvs[e * 70 + kB] : 1.f;
                const float4* rp = (const float4*)&rads[e * 120 + base];
                float4 p0 = rp[0], p1 = rp[1];
                accB[0] += g * p0.x; accB[1] += g * p0.y;
                accB[2] += g * p0.z; accB[3] += g * p0.w;
                accB[4] += g * p1.x; accB[5] += g * p1.y;
                accB[6] += g * p1.z; accB[7] += g * p1.w;
            }
        }
        __syncthreads();
    }

    if (actB) {
#pragma unroll
        for (int q = 0; q < 8; q++) gis[kB * 24 + r0B + q] = accB[q];
    }
    __syncthreads();

    // features: [feat0 | z1+ z1- | z2+ z2- | z3+ z3- | z4+ z4-], 24 each
    if (tid < FDIM) {
        int grp = tid / NRADB, r = tid % NRADB;
        float v;
        if (grp == 0) {
            v = gis[KTOT * 24 + r];
        } else {
            int iz = (grp - 1) >> 1;
            int neg = (grp - 1) & 1;
            float ssum = 0.f;
            for (int k = KOFF[iz]; k < KOFF[iz + 1]; k++) {
                float g = gis[k * 24 + r];
                ssum += g * g * (neg ? g_lam[k] : 1.f);
            }
            v = ssum * (1.0f / (float)(1 << iz));
        }
        d_feat[a * FDIM + tid] = v;
    }
}

// ---------------- Wa1 -> transposed bf16 hi/lo [256][3456] ----------------
__global__ void conv_w1_kernel(const float* __restrict__ Wa1) {
    __shared__ float t[32][33];
    int k0 = blockIdx.x * 32, n0 = blockIdx.y * 32;
    int tx = threadIdx.x, ty = threadIdx.y;   // 32 x 8
#pragma unroll
    for (int r = 0; r < 32; r += 8)
        t[ty + r][tx] = Wa1[(size_t)(k0 + ty + r) * 256 + n0 + tx];
    __syncthreads();
#pragma unroll
    for (int r = 0; r < 32; r += 8) {
        int n = n0 + ty + r, k = k0 + tx;
        float v = t[tx][ty + r];
        __nv_bfloat16 h = __float2bfloat16(v);
        d_Bt_hi[(size_t)n * KTOTAL + k] = h;
        d_Bt_lo[(size_t)n * KTOTAL + k] = __float2bfloat16(v - __bfloat162float(h));
    }
}

// ---------------- X = feat (x) emb -> bf16 hi/lo [2048][3456] ----------------
__global__ void xgen_kernel(const float* __restrict__ feat, const float* __restrict__ emb) {
    int t = blockIdx.x * blockDim.x + threadIdx.x;   // NATOM*432 threads, 8 k each
    int a = t / 432, rem = t % 432;
    int k0 = rem * 8;
    float f = feat[a * FDIM + (k0 >> 4)];
    const float4* ep = (const float4*)(emb + a * EMBD + (k0 & 15));
    float4 e0 = ep[0], e1 = ep[1];
    float v[8] = {f * e0.x, f * e0.y, f * e0.z, f * e0.w,
                  f * e1.x, f * e1.y, f * e1.z, f * e1.w};
    uint4 uh, ul;
    uint32_t* ph = (uint32_t*)&uh;
    uint32_t* pl = (uint32_t*)&ul;
#pragma unroll
    for (int i = 0; i < 4; i++) {
        __nv_bfloat16 h0 = __float2bfloat16(v[2 * i]);
        __nv_bfloat16 h1 = __float2bfloat16(v[2 * i + 1]);
        __nv_bfloat162 hh = __halves2bfloat162(h0, h1);
        __nv_bfloat162 ll = __halves2bfloat162(
            __float2bfloat16(v[2 * i] - __bfloat162float(h0)),
            __float2bfloat16(v[2 * i + 1] - __bfloat162float(h1)));
        ph[i] = *(uint32_t*)&hh;
        pl[i] = *(uint32_t*)&ll;
    }
    *(uint4*)&d_Xh[(size_t)a * KTOTAL + k0] = uh;
    *(uint4*)&d_Xl[(size_t)a * KTOTAL + k0] = ul;
}

// ---------------- GEMM1: double-buffered ldmatrix mma pipeline ----------------
// h1parts[kseg] = X @ Wa1 partial (3-pass bf16 split). BM=128, BN=64, BK=32;
// 8 warps (4x2), warp 32x32; split-K over blockIdx.z, partials to distinct buffers.
#define LDA 40           // row stride 80 B: 16B-aligned, all-32-bank coverage
#define A_HI_O 0
#define A_LO_O 10240
#define B_HI_O 20480
#define B_LO_O 25600
#define SBUF   30720
__global__ __launch_bounds__(256) void gemm1_mma_kernel(
    const __nv_bfloat16* __restrict__ Xh, const __nv_bfloat16* __restrict__ Xl,
    const __nv_bfloat16* __restrict__ Bth, const __nv_bfloat16* __restrict__ Btl,
    float* __restrict__ outp)
{
    extern __shared__ char smem[];
    uint32_t sb = smem_u32(smem);
    int tid = threadIdx.x;
    int warp = tid >> 5, lane = tid & 31;
    int wm0 = (warp >> 1) * 32, wn0 = (warp & 1) * 32;
    int mtile = blockIdx.x, ntile = blockIdx.y, kseg = blockIdx.z;

    int lrow = (lane & 7) + ((lane >> 3) & 1) * 8;
    int lcol = (lane >> 4) * 8;

    int arow = tid >> 1, aq = tid & 1;       // A: row, 16-k half
    int brow = tid >> 2, bq = tid & 3;       // B: row, 8-k quarter
    size_t gA = (size_t)(mtile * 128 + arow) * KTOTAL;
    size_t gB = (size_t)(ntile * 64 + brow) * KTOTAL;

    uint4 vah0, vah1, val0, val1, vbh, vbl;
    auto ldg = [&](int it) {
        int k0 = (kseg * ITERS + it) * 32;
        vah0 = *(const uint4*)(Xh + gA + k0 + aq * 16);
        vah1 = *(const uint4*)(Xh + gA + k0 + aq * 16 + 8);
        val0 = *(const uint4*)(Xl + gA + k0 + aq * 16);
        val1 = *(const uint4*)(Xl + gA + k0 + aq * 16 + 8);
        vbh  = *(const uint4*)(Bth + gB + k0 + bq * 8);
        vbl  = *(const uint4*)(Btl + gB + k0 + bq * 8);
    };
    auto sts = [&](int buf) {
        char* base = smem + buf * SBUF;
        int ao = arow * 80 + aq * 32;
        *(uint4*)(base + A_HI_O + ao)      = vah0;
        *(uint4*)(base + A_HI_O + ao + 16) = vah1;
        *(uint4*)(base + A_LO_O + ao)      = val0;
        *(uint4*)(base + A_LO_O + ao + 16) = val1;
        int bo = brow * 80 + bq * 16;
        *(uint4*)(base + B_HI_O + bo) = vbh;
        *(uint4*)(base + B_LO_O + bo) = vbl;
    };

    float acc[2][4][4];
#pragma unroll
    for (int i = 0; i < 2; i++)
#pragma unroll
        for (int j = 0; j < 4; j++)
#pragma unroll
            for (int q = 0; q < 4; q++) acc[i][j][q] = 0.f;

    ldg(0);
    sts(0);
    __syncthreads();

    for (int it = 0; it < ITERS; it++) {
        int buf = it & 1;
        bool more = (it + 1) < ITERS;
        if (more) ldg(it + 1);
        uint32_t aH = sb + buf * SBUF + A_HI_O;
        uint32_t aL = sb + buf * SBUF + A_LO_O;
        uint32_t bH = sb + buf * SBUF + B_HI_O;
        uint32_t bL = sb + buf * SBUF + B_LO_O;
#pragma unroll
        for (int kk = 0; kk < 2; kk++) {
            int kcol = kk * 16 + lcol;
            uint32_t ah[2][4], al[2][4], bh[4][2], bl[4][2];
#pragma unroll
            for (int i = 0; i < 2; i++) {
                uint32_t off = (uint32_t)(((wm0 + i * 16 + lrow) * LDA + kcol) * 2);
                ldsm4(ah[i], aH + off);
                ldsm4(al[i], aL + off);
            }
#pragma unroll
            for (int j2 = 0; j2 < 2; j2++) {
                uint32_t off = (uint32_t)(((wn0 + j2 * 16 + lrow) * LDA + kcol) * 2);
                uint32_t t[4];
                ldsm4(t, bH + off);
                bh[2 * j2][0] = t[0]; bh[2 * j2 + 1][0] = t[1];
                bh[2 * j2][1] = t[2]; bh[2 * j2 + 1][1] = t[3];
                ldsm4(t, bL + off);
                bl[2 * j2][0] = t[0]; bl[2 * j2 + 1][0] = t[1];
                bl[2 * j2][1] = t[2]; bl[2 * j2 + 1][1] = t[3];
            }
#pragma unroll
            for (int i = 0; i < 2; i++)
#pragma unroll
                for (int j = 0; j < 4; j++) {
                    mma16816(acc[i][j], ah[i], bh[j]);
                    mma16816(acc[i][j], al[i], bh[j]);
                    mma16816(acc[i][j], ah[i], bl[j]);
                }
        }
        if (more) sts(buf ^ 1);
        __syncthreads();
    }

    // ---- epilogue: plain stores to this kseg's partial buffer ----
    float* dst = outp + (size_t)kseg * NATOM * 256;
    int gid = lane >> 2, tig = lane & 3;
#pragma unroll
    for (int i = 0; i < 2; i++) {
        int r0 = mtile * 128 + wm0 + i * 16 + gid;
#pragma unroll
        for (int j = 0; j < 4; j++) {
            int cn = ntile * 64 + wn0 + j * 8 + tig * 2;
            *(float2*)(dst + (size_t)r0 * 256 + cn) = make_float2(acc[i][j][0], acc[i][j][1]);
            *(float2*)(dst + (size_t)(r0 + 8) * 256 + cn) = make_float2(acc[i][j][2], acc[i][j][3]);
        }
    }
}

__global__ void bias_silu_kernel(const float* __restrict__ ba1) {
    int i = blockIdx.x * blockDim.x + threadIdx.x;
    float s = d_h1parts[i] + d_h1parts[i + NATOM * 256]
            + d_h1parts[i + 2 * NATOM * 256] + d_h1parts[i + 3 * NATOM * 256];
    d_h1[i] = silu_f(s + ba1[i & 255]);
}

// ---------------- fp32 GEMM2 + bias + silu ----------------
__global__ __launch_bounds__(256) void gemm_silu_k(
    const float* __restrict__ A, const float* __restrict__ B,
    const float* __restrict__ bias, float* __restrict__ C,
    int M, int N, int K)
{
    const int BM = 64, BN = 64, BK = 32;
    __shared__ float As[BK][BM + 1];
    __shared__ float Bs[BK][BN + 1];
    int tid = threadIdx.x;
    int tx = tid % 16, ty = tid / 16;
    int row0 = blockIdx.x * BM, col0 = blockIdx.y * BN;
    float accum[4][4];
#pragma unroll
    for (int i = 0; i < 4; i++)
#pragma unroll
        for (int j = 0; j < 4; j++) accum[i][j] = 0.f;

    for (int k0 = 0; k0 < K; k0 += BK) {
        for (int i = tid; i < BM * BK; i += 256) {
            int m = i / BK, k = i % BK;
            As[k][m] = A[(size_t)(row0 + m) * K + k0 + k];
        }
        for (int i = tid; i < BK * BN; i += 256) {
            int k = i / BN, n = i % BN;
            Bs[k][n] = B[(size_t)(k0 + k) * N + col0 + n];
        }
        __syncthreads();
#pragma unroll
        for (int k = 0; k < BK; k++) {
            float av[4], bv[4];
#pragma unroll
            for (int i = 0; i < 4; i++) av[i] = As[k][ty * 4 + i];
#pragma unroll
            for (int j = 0; j < 4; j++) bv[j] = Bs[k][tx * 4 + j];
#pragma unroll
            for (int i = 0; i < 4; i++)
#pragma unroll
                for (int j = 0; j < 4; j++) accum[i][j] += av[i] * bv[j];
        }
        __syncthreads();
    }
#pragma unroll
    for (int i = 0; i < 4; i++) {
        int row = row0 + ty * 4 + i;
#pragma unroll
        for (int j = 0; j < 4; j++) {
            int col = col0 + tx * 4 + j;
            C[(size_t)row * N + col] = silu_f(accum[i][j] + bias[col]);
        }
    }
}

// ---------------- final reduction ----------------
__global__ void zero_out_k(float* out) { out[0] = 0.f; }

__global__ void final_kernel(const float* __restrict__ Wa3,
                             const float* __restrict__ ba3, float* out) {
    int gt = blockIdx.x * blockDim.x + threadIdx.x;
    int a = gt >> 5, lane = gt & 31;
    if (a < NATOM) {
        float s = 0.f;
#pragma unroll
        for (int i = lane; i < 128; i += 32) s += d_h2[a * 128 + i] * Wa3[i];
#pragma unroll
        for (int o = 16; o; o >>= 1) s += __shfl_xor_sync(0xffffffffu, s, o);
        if (lane == 0) atomicAdd(out, s + ba3[0]);
    }
}

// ---------------- launch ----------------
extern "C" void kernel_launch(void* const* d_in, const int* in_sizes, int n_in,
                              void* d_out, int out_size) {
    (void)in_sizes; (void)n_in; (void)out_size;
    const float* rij = (const float*)d_in[0];
    const float* Wr1 = (const float*)d_in[1];
    const float* br1 = (const float*)d_in[2];
    const float* Wr2 = (const float*)d_in[3];
    const float* br2 = (const float*)d_in[4];
    const float* Ws1 = (const float*)d_in[5];
    const float* bs1 = (const float*)d_in[6];
    const float* Ws2 = (const float*)d_in[7];
    const float* bs2 = (const float*)d_in[8];
    const float* Wa1 = (const float*)d_in[9];
    const float* ba1 = (const float*)d_in[10];
    const float* Wa2 = (const float*)d_in[11];
    const float* ba2 = (const float*)d_in[12];
    const float* Wa3 = (const float*)d_in[13];
    const float* ba3 = (const float*)d_in[14];
    const int*   fia     = (const int*)d_in[15];
    const int*   species = (const int*)d_in[16];
    float* out = (float*)d_out;

    void *p_feat, *p_emb, *p_parts, *p_h1, *p_h2, *p_bth, *p_btl, *p_xh, *p_xl;
    cudaGetSymbolAddress(&p_feat,  d_feat);
    cudaGetSymbolAddress(&p_emb,   d_emb);
    cudaGetSymbolAddress(&p_parts, d_h1parts);
    cudaGetSymbolAddress(&p_h1,    d_h1);
    cudaGetSymbolAddress(&p_h2,    d_h2);
    cudaGetSymbolAddress(&p_bth,   d_Bt_hi);
    cudaGetSymbolAddress(&p_btl,   d_Bt_lo);
    cudaGetSymbolAddress(&p_xh,    d_Xh);
    cudaGetSymbolAddress(&p_xl,    d_Xl);

    init_tables<<<1, 1>>>();                               // launch 0
    seg_kernel<<<(NATOM + 1 + 255) / 256, 256>>>(fia);     // launch 1
    conv_w1_kernel<<<dim3(KTOTAL / 32, 256 / 32), dim3(32, 8)>>>(Wa1);  // launch 2

    // feature smem: see layout comment in kernel
    const int SMEMB = (1536 + 64 + 7680 + 120 + TILE * 120 + TILE * 70 + 70 * 24 +
                       8 * 352 + 32 + KTOT + KTOT) * 4;
    cudaFuncSetAttribute(feature_kernel, cudaFuncAttributeMaxDynamicSharedMemorySize, SMEMB);
    feature_kernel<<<NATOM, 256, SMEMB>>>(rij, Wr1, br1, Wr2, br2,
                                          Ws1, bs1, Ws2, bs2, species);   // launch 3 (profiled)

    xgen_kernel<<<NATOM * 432 / 256, 256>>>((const float*)p_feat, (const float*)p_emb);

    const int G1SMEM = 2 * SBUF;
    cudaFuncSetAttribute(gemm1_mma_kernel, cudaFuncAttributeMaxDynamicSharedMemorySize, G1SMEM);
    gemm1_mma_kernel<<<dim3(NATOM / 128, 256 / 64, KSPLIT), 256, G1SMEM>>>(
        (const __nv_bfloat16*)p_xh, (const __nv_bfloat16*)p_xl,
        (const __nv_bfloat16*)p_bth, (const __nv_bfloat16*)p_btl,
        (float*)p_parts);

    bias_silu_kernel<<<NATOM * 256 / 256, 256>>>(ba1);

    gemm_silu_k<<<dim3(NATOM / 64, 128 / 64), 256>>>(
        (const float*)p_h1, Wa2, ba2, (float*)p_h2, NATOM, 128, 256);

    zero_out_k<<<1, 1>>>(out);
    final_kernel<<<NATOM * 32 / 256, 256>>>(Wa3, ba3, out);
}

// round 10
// speedup vs baseline: 2.3346x; 1.1028x over previous
#include <cuda_runtime.h>
#include <cuda_bf16.h>
#include <math.h>
#include <cstdint>

#define NEDGE 65536
#define NATOM 2048
#define NRADB 24
#define NCOMP 5
#define KTOT  69
#define FDIM  216            // 24 * 9
#define EMBD  16
#define TILE  32
#define KTOTAL 3456          // FDIM * EMBD
#define KSPLIT 4
#define ITERS  27            // KTOTAL / KSPLIT / 32

// ---------------- scratch (static device globals) ----------------
__device__ int   g_lx[KTOT], g_ly[KTOT], g_lz[KTOT], g_izk[KTOT];
__device__ float g_fnorm[KTOT], g_lam[KTOT];
__constant__ int KOFF[5] = {0, 4, 14, 34, 69};

__device__ int   d_seg[NATOM + 1];
__device__ float d_emb[NATOM * EMBD];
__device__ float d_feat[NATOM * FDIM];
__device__ float d_h1parts[KSPLIT * NATOM * 256];
__device__ float d_h1[NATOM * 256];
__device__ float d_h2[NATOM * 128];
__device__ __nv_bfloat16 d_Bt_hi[256 * KTOTAL];
__device__ __nv_bfloat16 d_Bt_lo[256 * KTOTAL];
__device__ __nv_bfloat16 d_Xh[NATOM * KTOTAL];
__device__ __nv_bfloat16 d_Xl[NATOM * KTOTAL];
// edge-pipeline scratch
__device__ __nv_bfloat16 d_hh[NEDGE * 64];
__device__ __nv_bfloat16 d_hl[NEDGE * 64];
__device__ float d_gv[NEDGE * 72];
__device__ float d_rad[NEDGE * 120];
__device__ __nv_bfloat16 d_Bt2_hi[128 * 64];
__device__ __nv_bfloat16 d_Bt2_lo[128 * 64];
__device__ float d_br2p[120];

__device__ __forceinline__ float silu_f(float x) { return x / (1.f + expf(-x)); }

__device__ __forceinline__ float powi(float b, int l) {
    float r = 1.f;
#pragma unroll
    for (int i = 0; i < 4; i++) if (i < l) r *= b;
    return r;
}

// bf16 mma.sync (family-portable; legacy HMMA pipe on Blackwell)
__device__ __forceinline__ void mma16816(float* c, const uint32_t* a, const uint32_t* b) {
    asm volatile(
        "mma.sync.aligned.m16n8k16.row.col.f32.bf16.bf16.f32 "
        "{%0,%1,%2,%3}, {%4,%5,%6,%7}, {%8,%9}, {%0,%1,%2,%3};"
        : "+f"(c[0]), "+f"(c[1]), "+f"(c[2]), "+f"(c[3])
        : "r"(a[0]), "r"(a[1]), "r"(a[2]), "r"(a[3]), "r"(b[0]), "r"(b[1]));
}

__device__ __forceinline__ void ldsm4(uint32_t* r, uint32_t addr) {
    asm volatile("ldmatrix.sync.aligned.m8n8.x4.shared.b16 {%0,%1,%2,%3}, [%4];"
                 : "=r"(r[0]), "=r"(r[1]), "=r"(r[2]), "=r"(r[3]) : "r"(addr));
}

__device__ __forceinline__ uint32_t smem_u32(const void* p) {
    uint32_t a;
    asm("{ .reg .u64 t; cvta.to.shared.u64 t, %1; cvt.u32.u64 %0, t; }" : "=r"(a) : "l"(p));
    return a;
}

// ---------------- table init ----------------
__global__ void init_tables() {
    if (threadIdx.x == 0 && blockIdx.x == 0) {
        const int fact[5] = {1, 1, 2, 6, 24};
        int idx = 0;
        for (int iz = 0; iz < 4; iz++) {
            int z = iz + 1;
            for (int n = 0; n <= z; n++)
                for (int lx = 0; lx <= n; lx++)
                    for (int ly = 0; ly <= n - lx; ly++) {
                        int lz = n - lx - ly;
                        g_lx[idx] = lx; g_ly[idx] = ly; g_lz[idx] = lz;
                        g_izk[idx] = iz;
                        g_fnorm[idx] = (float)fact[z] /
                            (float)(fact[z - n] * fact[lx] * fact[ly] * fact[lz]);
                        g_lam[idx] = (n & 1) ? -1.f : 1.f;
                        idx++;
                    }
        }
    }
}

// ---------------- segment offsets ----------------
__global__ void seg_kernel(const int* __restrict__ fia) {
    int a = blockIdx.x * blockDim.x + threadIdx.x;
    if (a <= NATOM) {
        int lo = 0, hi = NEDGE;
        while (lo < hi) {
            int mid = (lo + hi) >> 1;
            if (fia[mid] < a) lo = mid + 1; else hi = mid;
        }
        d_seg[a] = lo;
    }
}

// ---------------- Wr2 -> permuted-transposed bf16 hi/lo [128 n][64 k] ----------------
// n = (j%5)*24 + j/5 permutation; rows 120-127 zero. Also permuted bias.
__global__ void conv_w2_kernel(const float* __restrict__ Wr2, const float* __restrict__ br2) {
    int i = blockIdx.x * blockDim.x + threadIdx.x;
    if (i < 128 * 64) {
        int n = i >> 6, k = i & 63;
        float v = 0.f;
        if (n < 120) {
            int j = (n % 24) * 5 + n / 24;
            v = Wr2[k * 120 + j];
        }
        __nv_bfloat16 h = __float2bfloat16(v);
        d_Bt2_hi[i] = h;
        d_Bt2_lo[i] = __float2bfloat16(v - __bfloat162float(h));
        if (k == 0 && n < 120) d_br2p[n] = br2[(n % 24) * 5 + n / 24];
    }
}

// ---------------- edge kernel: geometry + basis + MLP1 + angular ----------------
// 8 warps x 4 edges per CTA; 2048 CTAs cover all 65536 edges (always full).
__global__ __launch_bounds__(256) void edge_kernel(
    const float* __restrict__ rij,
    const float* __restrict__ Wr1, const float* __restrict__ br1)
{
    __shared__ float Wr1s[NRADB * 64];
    __shared__ float br1s[64];
    __shared__ float basw_s[8][96];
    __shared__ int   slk[KTOT];
    __shared__ float sfn[KTOT];

    int tid = threadIdx.x;
    int wid = tid >> 5, lane = tid & 31;

    for (int i = tid; i < NRADB * 64; i += 256) Wr1s[i] = Wr1[i];
    if (tid < 64) br1s[tid] = br1[tid];
    if (tid < KTOT) {
        slk[tid] = g_lx[tid] | (g_ly[tid] << 8) | (g_lz[tid] << 16);
        sfn[tid] = g_fnorm[tid];
    }
    __syncthreads();

    int e0 = blockIdx.x * 32 + wid * 4;
    float* basw = basw_s[wid];

    // geometry: lanes 0-3, one edge each
    float rE = 0.f, uxE = 0.f, uyE = 0.f, uzE = 0.f, fcE = 0.f;
    if (lane < 4) {
        int e = e0 + lane;
        float x = rij[e * 3], y = rij[e * 3 + 1], z = rij[e * 3 + 2];
        float r = sqrtf(x * x + y * y + z * z);
        float inv = 1.f / r;
        rE = r;
        uxE = x * inv + 1e-12f;
        uyE = y * inv + 1e-12f;
        uzE = z * inv + 1e-12f;
        float rc = fminf(r, 6.f);
        fcE = 0.5f * (cosf(rc * 0.52359877559829887f) + 1.f);
    }
    // basis: lane -> edge lane>>3, k = (lane&7)+{0,8,16}
    {
        int ge = lane >> 3;
        float rB  = __shfl_sync(0xffffffffu, rE, ge);
        float fcB = __shfl_sync(0xffffffffu, fcE, ge);
#pragma unroll
        for (int q = 0; q < 3; q++) {
            int k = (lane & 7) + q * 8;
            float d = rB - (6.f / 23.f) * (float)k;
            basw[ge * 24 + k] = expf(-8.f * d * d) * fcB;
        }
    }
    __syncwarp();
    // MLP1 joint: lane -> outputs 2*lane, 2*lane+1 for 4 edges; write bf16 hi/lo
    {
        float a0[4], a1[4];
#pragma unroll
        for (int e = 0; e < 4; e++) { a0[e] = 0.f; a1[e] = 0.f; }
#pragma unroll 6
        for (int k = 0; k < NRADB; k++) {
            float2 w = *(const float2*)&Wr1s[k * 64 + 2 * lane];
            float b0 = basw[k], b1 = basw[24 + k], b2 = basw[48 + k], b3 = basw[72 + k];
            a0[0] += b0 * w.x; a1[0] += b0 * w.y;
            a0[1] += b1 * w.x; a1[1] += b1 * w.y;
            a0[2] += b2 * w.x; a1[2] += b2 * w.y;
            a0[3] += b3 * w.x; a1[3] += b3 * w.y;
        }
        float2 bb = *(const float2*)&br1s[2 * lane];
#pragma unroll
        for (int e = 0; e < 4; e++) {
            float h0 = silu_f(a0[e] + bb.x);
            float h1 = silu_f(a1[e] + bb.y);
            __nv_bfloat16 H0 = __float2bfloat16(h0);
            __nv_bfloat16 H1 = __float2bfloat16(h1);
            size_t off = (size_t)(e0 + e) * 64 + 2 * lane;
            *(__nv_bfloat162*)&d_hh[off] = __halves2bfloat162(H0, H1);
            *(__nv_bfloat162*)&d_hl[off] = __halves2bfloat162(
                __float2bfloat16(h0 - __bfloat162float(H0)),
                __float2bfloat16(h1 - __bfloat162float(H1)));
        }
    }
    // angular monomials per edge -> d_gv[e][72]
#pragma unroll
    for (int e4 = 0; e4 < 4; e4++) {
        float ux = __shfl_sync(0xffffffffu, uxE, e4);
        float uy = __shfl_sync(0xffffffffu, uyE, e4);
        float uz = __shfl_sync(0xffffffffu, uzE, e4);
#pragma unroll
        for (int q = 0; q < 3; q++) {
            int k = lane + q * 32;
            if (k < KTOT) {
                int pk = slk[k];
                d_gv[(size_t)(e0 + e4) * 72 + k] = sfn[k] *
                    powi(ux, pk & 255) * powi(uy, (pk >> 8) & 255) * powi(uz, pk >> 16);
            }
        }
    }
}

// ---------------- MLP2 GEMM: rad = silu(h @ Wr2p + b), 3-pass bf16 split ----------------
// M=65536, N=120 (pad 128), K=64 single-shot. BM=128; 8 warps, warp = m16 x n128.
#define E2_LDA 72        // elems; row stride 144 B (16B-aligned, ldsm conflict-free)
#define E2_AH 0
#define E2_AL 18432
#define E2_BH 36864
#define E2_BL 55296
#define E2_SMEM 73728
__global__ __launch_bounds__(256) void mlp2_gemm_kernel(
    const __nv_bfloat16* __restrict__ hh, const __nv_bfloat16* __restrict__ hl,
    float* __restrict__ rad)
{
    extern __shared__ char smem[];
    uint32_t sb = smem_u32(smem);
    int tid = threadIdx.x;
    int warp = tid >> 5, lane = tid & 31;
    int e0 = blockIdx.x * 128;

    // load A (h tile 128x64) and B (Wr2p 128x64)
    for (int i = tid; i < 1024; i += 256) {
        int row = i >> 3, ch = i & 7;
        size_t ga = (size_t)(e0 + row) * 64 + ch * 8;
        *(uint4*)(smem + E2_AH + row * 144 + ch * 16) = *(const uint4*)(hh + ga);
        *(uint4*)(smem + E2_AL + row * 144 + ch * 16) = *(const uint4*)(hl + ga);
        *(uint4*)(smem + E2_BH + row * 144 + ch * 16) = *(const uint4*)(d_Bt2_hi + row * 64 + ch * 8);
        *(uint4*)(smem + E2_BL + row * 144 + ch * 16) = *(const uint4*)(d_Bt2_lo + row * 64 + ch * 8);
    }
    __syncthreads();

    int m0 = warp * 16;
    int lrow = (lane & 7) + ((lane >> 3) & 1) * 8;
    int lcol = (lane >> 4) * 8;

    float acc[16][4];
#pragma unroll
    for (int j = 0; j < 16; j++)
#pragma unroll
        for (int q = 0; q < 4; q++) acc[j][q] = 0.f;

#pragma unroll
    for (int kst = 0; kst < 4; kst++) {
        int kcol = kst * 16 + lcol;
        uint32_t ah[4], al[4];
        ldsm4(ah, sb + E2_AH + ((m0 + lrow) * E2_LDA + kcol) * 2);
        ldsm4(al, sb + E2_AL + ((m0 + lrow) * E2_LDA + kcol) * 2);
#pragma unroll
        for (int nb = 0; nb < 8; nb++) {
            uint32_t th[4], tl[4];
            ldsm4(th, sb + E2_BH + ((nb * 16 + lrow) * E2_LDA + kcol) * 2);
            ldsm4(tl, sb + E2_BL + ((nb * 16 + lrow) * E2_LDA + kcol) * 2);
            uint32_t b0h[2] = {th[0], th[2]}, b1h[2] = {th[1], th[3]};
            uint32_t b0l[2] = {tl[0], tl[2]}, b1l[2] = {tl[1], tl[3]};
            mma16816(acc[2 * nb],     ah, b0h);
            mma16816(acc[2 * nb],     al, b0h);
            mma16816(acc[2 * nb],     ah, b0l);
            mma16816(acc[2 * nb + 1], ah, b1h);
            mma16816(acc[2 * nb + 1], al, b1h);
            mma16816(acc[2 * nb + 1], ah, b1l);
        }
    }

    // epilogue: silu + bias, positions j<15 (cols < 120)
    int gid = lane >> 2, tig = lane & 3;
#pragma unroll
    for (int j = 0; j < 15; j++) {
        int cn = j * 8 + tig * 2;
        float b0 = d_br2p[cn], b1 = d_br2p[cn + 1];
        int r0 = e0 + m0 + gid;
        *(float2*)(rad + (size_t)r0 * 120 + cn) =
            make_float2(silu_f(acc[j][0] + b0), silu_f(acc[j][1] + b1));
        *(float2*)(rad + (size_t)(r0 + 8) * 120 + cn) =
            make_float2(silu_f(acc[j][2] + b0), silu_f(acc[j][3] + b1));
    }
}

// ---------------- per-atom moment kernel: stage + phase B + feature epilogue ----------------
__global__ __launch_bounds__(256) void moment_kernel(
    const float* __restrict__ rad, const float* __restrict__ gv,
    const float* __restrict__ Ws1, const float* __restrict__ bs1,
    const float* __restrict__ Ws2, const float* __restrict__ bs2,
    const int* __restrict__ species)
{
    __shared__ float rads[TILE * 120];
    __shared__ float gvs[TILE * 72];
    __shared__ float gis[70 * 24];
    __shared__ float hsp[32];

    int tid = threadIdx.x;
    int a = blockIdx.x;

    int sidx = species[a];
    if (tid < 32) hsp[tid] = silu_f(Ws1[sidx * 32 + tid] + bs1[tid]);
    __syncthreads();
    if (tid < EMBD) {
        float acc = bs2[tid];
        for (int i = 0; i < 32; i++) acc += hsp[i] * Ws2[i * EMBD + tid];
        d_emb[a * EMBD + tid] = acc;
    }

    bool actB = tid < 210;
    int kB = tid / 3, r0B = (tid % 3) * 8, cB = 0;
    if (actB) cB = (kB < 4) ? 1 : (kB < 14) ? 2 : (kB < 34) ? 3 : (kB < 69) ? 4 : 0;
    float accB[8];
#pragma unroll
    for (int q = 0; q < 8; q++) accB[q] = 0.f;

    int beg = d_seg[a], end = d_seg[a + 1];

    for (int pos = beg; pos < end; pos += TILE) {
        int nE = min(TILE, end - pos);
        // stage rad rows (30 float4 each) and gv rows (18 float4 each)
        for (int i = tid; i < nE * 30; i += 256) {
            int row = i / 30, ch = i % 30;
            *(float4*)&rads[row * 120 + ch * 4] =
                *(const float4*)(rad + (size_t)(pos + row) * 120 + ch * 4);
        }
        for (int i = tid; i < nE * 18; i += 256) {
            int row = i / 18, ch = i % 18;
            *(float4*)&gvs[row * 72 + ch * 4] =
                *(const float4*)(gv + (size_t)(pos + row) * 72 + ch * 4);
        }
        __syncthreads();
        if (actB) {
            int base = cB * 24 + r0B;
            for (int e = 0; e < nE; e++) {
                float g = (kB < KTOT) ? gvs[e * 72 + kB] : 1.f;
                const float4* rp = (const float4*)&rads[e * 120 + base];
                float4 p0 = rp[0], p1 = rp[1];
                accB[0] += g * p0.x; accB[1] += g * p0.y;
                accB[2] += g * p0.z; accB[3] += g * p0.w;
                accB[4] += g * p1.x; accB[5] += g * p1.y;
                accB[6] += g * p1.z; accB[7] += g * p1.w;
            }
        }
        __syncthreads();
    }

    if (actB) {
#pragma unroll
        for (int q = 0; q < 8; q++) gis[kB * 24 + r0B + q] = accB[q];
    }
    __syncthreads();

    if (tid < FDIM) {
        int grp = tid / NRADB, r = tid % NRADB;
        float v;
        if (grp == 0) {
            v = gis[KTOT * 24 + r];
        } else {
            int iz = (grp - 1) >> 1;
            int neg = (grp - 1) & 1;
            float ssum = 0.f;
            for (int k = KOFF[iz]; k < KOFF[iz + 1]; k++) {
                float g = gis[k * 24 + r];
                ssum += g * g * (neg ? g_lam[k] : 1.f);
            }
            v = ssum * (1.0f / (float)(1 << iz));
        }
        d_feat[a * FDIM + tid] = v;
    }
}

// ---------------- Wa1 -> transposed bf16 hi/lo [256][3456] ----------------
__global__ void conv_w1_kernel(const float* __restrict__ Wa1) {
    __shared__ float t[32][33];
    int k0 = blockIdx.x * 32, n0 = blockIdx.y * 32;
    int tx = threadIdx.x, ty = threadIdx.y;   // 32 x 8
#pragma unroll
    for (int r = 0; r < 32; r += 8)
        t[ty + r][tx] = Wa1[(size_t)(k0 + ty + r) * 256 + n0 + tx];
    __syncthreads();
#pragma unroll
    for (int r = 0; r < 32; r += 8) {
        int n = n0 + ty + r, k = k0 + tx;
        float v = t[tx][ty + r];
        __nv_bfloat16 h = __float2bfloat16(v);
        d_Bt_hi[(size_t)n * KTOTAL + k] = h;
        d_Bt_lo[(size_t)n * KTOTAL + k] = __float2bfloat16(v - __bfloat162float(h));
    }
}

// ---------------- X = feat (x) emb -> bf16 hi/lo [2048][3456] ----------------
__global__ void xgen_kernel(const float* __restrict__ feat, const float* __restrict__ emb) {
    int t = blockIdx.x * blockDim.x + threadIdx.x;   // NATOM*432 threads, 8 k each
    int a = t / 432, rem = t % 432;
    int k0 = rem * 8;
    float f = feat[a * FDIM + (k0 >> 4)];
    const float4* ep = (const float4*)(emb + a * EMBD + (k0 & 15));
    float4 e0 = ep[0], e1 = ep[1];
    float v[8] = {f * e0.x, f * e0.y, f * e0.z, f * e0.w,
                  f * e1.x, f * e1.y, f * e1.z, f * e1.w};
    uint4 uh, ul;
    uint32_t* ph = (uint32_t*)&uh;
    uint32_t* pl = (uint32_t*)&ul;
#pragma unroll
    for (int i = 0; i < 4; i++) {
        __nv_bfloat16 h0 = __float2bfloat16(v[2 * i]);
        __nv_bfloat16 h1 = __float2bfloat16(v[2 * i + 1]);
        __nv_bfloat162 hh = __halves2bfloat162(h0, h1);
        __nv_bfloat162 ll = __halves2bfloat162(
            __float2bfloat16(v[2 * i] - __bfloat162float(h0)),
            __float2bfloat16(v[2 * i + 1] - __bfloat162float(h1)));
        ph[i] = *(uint32_t*)&hh;
        pl[i] = *(uint32_t*)&ll;
    }
    *(uint4*)&d_Xh[(size_t)a * KTOTAL + k0] = uh;
    *(uint4*)&d_Xl[(size_t)a * KTOTAL + k0] = ul;
}

// ---------------- GEMM1: double-buffered ldmatrix mma pipeline ----------------
#define LDA 40
#define A_HI_O 0
#define A_LO_O 10240
#define B_HI_O 20480
#define B_LO_O 25600
#define SBUF   30720
__global__ __launch_bounds__(256) void gemm1_mma_kernel(
    const __nv_bfloat16* __restrict__ Xh, const __nv_bfloat16* __restrict__ Xl,
    const __nv_bfloat16* __restrict__ Bth, const __nv_bfloat16* __restrict__ Btl,
    float* __restrict__ outp)
{
    extern __shared__ char smem[];
    uint32_t sb = smem_u32(smem);
    int tid = threadIdx.x;
    int warp = tid >> 5, lane = tid & 31;
    int wm0 = (warp >> 1) * 32, wn0 = (warp & 1) * 32;
    int mtile = blockIdx.x, ntile = blockIdx.y, kseg = blockIdx.z;

    int lrow = (lane & 7) + ((lane >> 3) & 1) * 8;
    int lcol = (lane >> 4) * 8;

    int arow = tid >> 1, aq = tid & 1;
    int brow = tid >> 2, bq = tid & 3;
    size_t gA = (size_t)(mtile * 128 + arow) * KTOTAL;
    size_t gB = (size_t)(ntile * 64 + brow) * KTOTAL;

    uint4 vah0, vah1, val0, val1, vbh, vbl;
    auto ldg = [&](int it) {
        int k0 = (kseg * ITERS + it) * 32;
        vah0 = *(const uint4*)(Xh + gA + k0 + aq * 16);
        vah1 = *(const uint4*)(Xh + gA + k0 + aq * 16 + 8);
        val0 = *(const uint4*)(Xl + gA + k0 + aq * 16);
        val1 = *(const uint4*)(Xl + gA + k0 + aq * 16 + 8);
        vbh  = *(const uint4*)(Bth + gB + k0 + bq * 8);
        vbl  = *(const uint4*)(Btl + gB + k0 + bq * 8);
    };
    auto sts = [&](int buf) {
        char* base = smem + buf * SBUF;
        int ao = arow * 80 + aq * 32;
        *(uint4*)(base + A_HI_O + ao)      = vah0;
        *(uint4*)(base + A_HI_O + ao + 16) = vah1;
        *(uint4*)(base + A_LO_O + ao)      = val0;
        *(uint4*)(base + A_LO_O + ao + 16) = val1;
        int bo = brow * 80 + bq * 16;
        *(uint4*)(base + B_HI_O + bo) = vbh;
        *(uint4*)(base + B_LO_O + bo) = vbl;
    };

    float acc[2][4][4];
#pragma unroll
    for (int i = 0; i < 2; i++)
#pragma unroll
        for (int j = 0; j < 4; j++)
#pragma unroll
            for (int q = 0; q < 4; q++) acc[i][j][q] = 0.f;

    ldg(0);
    sts(0);
    __syncthreads();

    for (int it = 0; it < ITERS; it++) {
        int buf = it & 1;
        bool more = (it + 1) < ITERS;
        if (more) ldg(it + 1);
        uint32_t aH = sb + buf * SBUF + A_HI_O;
        uint32_t aL = sb + buf * SBUF + A_LO_O;
        uint32_t bH = sb + buf * SBUF + B_HI_O;
        uint32_t bL = sb + buf * SBUF + B_LO_O;
#pragma unroll
        for (int kk = 0; kk < 2; kk++) {
            int kcol = kk * 16 + lcol;
            uint32_t ah[2][4], al[2][4], bh[4][2], bl[4][2];
#pragma unroll
            for (int i = 0; i < 2; i++) {
                uint32_t off = (uint32_t)(((wm0 + i * 16 + lrow) * LDA + kcol) * 2);
                ldsm4(ah[i], aH + off);
                ldsm4(al[i], aL + off);
            }
#pragma unroll
            for (int j2 = 0; j2 < 2; j2++) {
                uint32_t off = (uint32_t)(((wn0 + j2 * 16 + lrow) * LDA + kcol) * 2);
                uint32_t t[4];
                ldsm4(t, bH + off);
                bh[2 * j2][0] = t[0]; bh[2 * j2 + 1][0] = t[1];
                bh[2 * j2][1] = t[2]; bh[2 * j2 + 1][1] = t[3];
                ldsm4(t, bL + off);
                bl[2 * j2][0] = t[0]; bl[2 * j2 + 1][0] = t[1];
                bl[2 * j2][1] = t[2]; bl[2 * j2 + 1][1] = t[3];
            }
#pragma unroll
            for (int i = 0; i < 2; i++)
#pragma unroll
                for (int j = 0; j < 4; j++) {
                    mma16816(acc[i][j], ah[i], bh[j]);
                    mma16816(acc[i][j], al[i], bh[j]);
                    mma16816(acc[i][j], ah[i], bl[j]);
                }
        }
        if (more) sts(buf ^ 1);
        __syncthreads();
    }

    float* dst = outp + (size_t)kseg * NATOM * 256;
    int gid = lane >> 2, tig = lane & 3;
#pragma unroll
    for (int i = 0; i < 2; i++) {
        int r0 = mtile * 128 + wm0 + i * 16 + gid;
#pragma unroll
        for (int j = 0; j < 4; j++) {
            int cn = ntile * 64 + wn0 + j * 8 + tig * 2;
            *(float2*)(dst + (size_t)r0 * 256 + cn) = make_float2(acc[i][j][0], acc[i][j][1]);
            *(float2*)(dst + (size_t)(r0 + 8) * 256 + cn) = make_float2(acc[i][j][2], acc[i][j][3]);
        }
    }
}

__global__ void bias_silu_kernel(const float* __restrict__ ba1) {
    int i = blockIdx.x * blockDim.x + threadIdx.x;
    float s = d_h1parts[i] + d_h1parts[i + NATOM * 256]
            + d_h1parts[i + 2 * NATOM * 256] + d_h1parts[i + 3 * NATOM * 256];
    d_h1[i] = silu_f(s + ba1[i & 255]);
}

// ---------------- fp32 GEMM2 + bias + silu ----------------
__global__ __launch_bounds__(256) void gemm_silu_k(
    const float* __restrict__ A, const float* __restrict__ B,
    const float* __restrict__ bias, float* __restrict__ C,
    int M, int N, int K)
{
    const int BM = 64, BN = 64, BK = 32;
    __shared__ float As[BK][BM + 1];
    __shared__ float Bs[BK][BN + 1];
    int tid = threadIdx.x;
    int tx = tid % 16, ty = tid / 16;
    int row0 = blockIdx.x * BM, col0 = blockIdx.y * BN;
    float accum[4][4];
#pragma unroll
    for (int i = 0; i < 4; i++)
#pragma unroll
        for (int j = 0; j < 4; j++) accum[i][j] = 0.f;

    for (int k0 = 0; k0 < K; k0 += BK) {
        for (int i = tid; i < BM * BK; i += 256) {
            int m = i / BK, k = i % BK;
            As[k][m] = A[(size_t)(row0 + m) * K + k0 + k];
        }
        for (int i = tid; i < BK * BN; i += 256) {
            int k = i / BN, n = i % BN;
            Bs[k][n] = B[(size_t)(k0 + k) * N + col0 + n];
        }
        __syncthreads();
#pragma unroll
        for (int k = 0; k < BK; k++) {
            float av[4], bv[4];
#pragma unroll
            for (int i = 0; i < 4; i++) av[i] = As[k][ty * 4 + i];
#pragma unroll
            for (int j = 0; j < 4; j++) bv[j] = Bs[k][tx * 4 + j];
#pragma unroll
            for (int i = 0; i < 4; i++)
#pragma unroll
                for (int j = 0; j < 4; j++) accum[i][j] += av[i] * bv[j];
        }
        __syncthreads();
    }
#pragma unroll
    for (int i = 0; i < 4; i++) {
        int row = row0 + ty * 4 + i;
#pragma unroll
        for (int j = 0; j < 4; j++) {
            int col = col0 + tx * 4 + j;
            C[(size_t)row * N + col] = silu_f(accum[i][j] + bias[col]);
        }
    }
}

// ---------------- final reduction ----------------
__global__ void zero_out_k(float* out) { out[0] = 0.f; }

__global__ void final_kernel(const float* __restrict__ Wa3,
                             const float* __restrict__ ba3, float* out) {
    int gt = blockIdx.x * blockDim.x + threadIdx.x;
    int a = gt >> 5, lane = gt & 31;
    if (a < NATOM) {
        float s = 0.f;
#pragma unroll
        for (int i = lane; i < 128; i += 32) s += d_h2[a * 128 + i] * Wa3[i];
#pragma unroll
        for (int o = 16; o; o >>= 1) s += __shfl_xor_sync(0xffffffffu, s, o);
        if (lane == 0) atomicAdd(out, s + ba3[0]);
    }
}

// ---------------- launch ----------------
extern "C" void kernel_launch(void* const* d_in, const int* in_sizes, int n_in,
                              void* d_out, int out_size) {
    (void)in_sizes; (void)n_in; (void)out_size;
    const float* rij = (const float*)d_in[0];
    const float* Wr1 = (const float*)d_in[1];
    const float* br1 = (const float*)d_in[2];
    const float* Wr2 = (const float*)d_in[3];
    const float* br2 = (const float*)d_in[4];
    const float* Ws1 = (const float*)d_in[5];
    const float* bs1 = (const float*)d_in[6];
    const float* Ws2 = (const float*)d_in[7];
    const float* bs2 = (const float*)d_in[8];
    const float* Wa1 = (const float*)d_in[9];
    const float* ba1 = (const float*)d_in[10];
    const float* Wa2 = (const float*)d_in[11];
    const float* ba2 = (const float*)d_in[12];
    const float* Wa3 = (const float*)d_in[13];
    const float* ba3 = (const float*)d_in[14];
    const int*   fia     = (const int*)d_in[15];
    const int*   species = (const int*)d_in[16];
    float* out = (float*)d_out;

    void *p_feat, *p_emb, *p_parts, *p_h1, *p_h2, *p_bth, *p_btl, *p_xh, *p_xl;
    void *p_hh, *p_hl, *p_gv, *p_rad;
    cudaGetSymbolAddress(&p_feat,  d_feat);
    cudaGetSymbolAddress(&p_emb,   d_emb);
    cudaGetSymbolAddress(&p_parts, d_h1parts);
    cudaGetSymbolAddress(&p_h1,    d_h1);
    cudaGetSymbolAddress(&p_h2,    d_h2);
    cudaGetSymbolAddress(&p_bth,   d_Bt_hi);
    cudaGetSymbolAddress(&p_btl,   d_Bt_lo);
    cudaGetSymbolAddress(&p_xh,    d_Xh);
    cudaGetSymbolAddress(&p_xl,    d_Xl);
    cudaGetSymbolAddress(&p_hh,    d_hh);
    cudaGetSymbolAddress(&p_hl,    d_hl);
    cudaGetSymbolAddress(&p_gv,    d_gv);
    cudaGetSymbolAddress(&p_rad,   d_rad);

    init_tables<<<1, 1>>>();                                        // 0
    conv_w2_kernel<<<(128 * 64 + 255) / 256, 256>>>(Wr2, br2);      // 1
    edge_kernel<<<NEDGE / 32, 256>>>(rij, Wr1, br1);                // 2

    cudaFuncSetAttribute(mlp2_gemm_kernel, cudaFuncAttributeMaxDynamicSharedMemorySize, E2_SMEM);
    mlp2_gemm_kernel<<<NEDGE / 128, 256, E2_SMEM>>>(                // 3 (profiled)
        (const __nv_bfloat16*)p_hh, (const __nv_bfloat16*)p_hl, (float*)p_rad);

    seg_kernel<<<(NATOM + 1 + 255) / 256, 256>>>(fia);              // 4
    moment_kernel<<<NATOM, 256>>>((const float*)p_rad, (const float*)p_gv,
                                  Ws1, bs1, Ws2, bs2, species);     // 5
    conv_w1_kernel<<<dim3(KTOTAL / 32, 256 / 32), dim3(32, 8)>>>(Wa1);  // 6
    xgen_kernel<<<NATOM * 432 / 256, 256>>>((const float*)p_feat, (const float*)p_emb);

    const int G1SMEM = 2 * SBUF;
    cudaFuncSetAttribute(gemm1_mma_kernel, cudaFuncAttributeMaxDynamicSharedMemorySize, G1SMEM);
    gemm1_mma_kernel<<<dim3(NATOM / 128, 256 / 64, KSPLIT), 256, G1SMEM>>>(
        (const __nv_bfloat16*)p_xh, (const __nv_bfloat16*)p_xl,
        (const __nv_bfloat16*)p_bth, (const __nv_bfloat16*)p_btl,
        (float*)p_parts);

    bias_silu_kernel<<<NATOM * 256 / 256, 256>>>(ba1);

    gemm_silu_k<<<dim3(NATOM / 64, 128 / 64), 256>>>(
        (const float*)p_h1, Wa2, ba2, (float*)p_h2, NATOM, 128, 256);

    zero_out_k<<<1, 1>>>(out);
    final_kernel<<<NATOM * 32 / 256, 256>>>(Wa3, ba3, out);
}